// round 6
// baseline (speedup 1.0000x reference)
#include <cuda_runtime.h>
#include <cuda_bf16.h>
#include <math.h>

// Problem constants
// N=16384 nodes, L=8 chain, D=256 in, H=256 hidden, R=64 rel
// Gate order (PyTorch): i, f, g, o

#define NTHREADS 256
#define BM 128
#define BN 128
#define BK 32

// Scratch (device globals — allocation-free rule)
__device__ float g_X[268435456];  // [2][8][16384][1024] : Xpre = x@Wih^T + (bih+bhh)
__device__ float g_h[16777216];   // [2 lstm][2 buf][16384][256]
__device__ float g_c[8388608];    // [2 lstm][16384][256]

struct SmemGemm {
  __nv_bfloat16 a_hi[BM][BK + 2];
  __nv_bfloat16 a_lo[BM][BK + 2];
  __nv_bfloat16 b_hi[BN][BK + 2];
  __nv_bfloat16 b_lo[BN][BK + 2];
};
union SmemU {
  SmemGemm g;
  float ep[64 * 132];  // epilogue half-tile (64 rows x 128 cols, padded stride 132)
};

__device__ __forceinline__ void mma16816(float* d, const unsigned* a, const unsigned* b) {
  asm volatile(
      "mma.sync.aligned.m16n8k16.row.col.f32.bf16.bf16.f32 "
      "{%0,%1,%2,%3}, {%4,%5,%6,%7}, {%8,%9}, {%0,%1,%2,%3};\n"
      : "+f"(d[0]), "+f"(d[1]), "+f"(d[2]), "+f"(d[3])
      : "r"(a[0]), "r"(a[1]), "r"(a[2]), "r"(a[3]), "r"(b[0]), "r"(b[1]));
}

// fp32 -> (hi, lo) bf16 split; 3 cross-products recover ~16-bit mantissa accuracy
__device__ __forceinline__ void split4(float4 v, __nv_bfloat16* hi, __nv_bfloat16* lo) {
  float x[4] = {v.x, v.y, v.z, v.w};
#pragma unroll
  for (int q = 0; q < 4; q++) {
    __nv_bfloat16 h = __float2bfloat16(x[q]);
    hi[q] = h;
    lo[q] = __float2bfloat16(x[q] - __bfloat162float(h));
  }
}

__device__ __forceinline__ float sigmoidf_(float x) { return 1.0f / (1.0f + expf(-x)); }

// One BK-chunk of the 128x128 warp-tiled GEMM (8 warps: wm in {0,1} x wn in {0..3};
// warp tile 64x32 = 4x4 m16n8 fragments). acc += Ahi*Bhi + Ahi*Blo + Alo*Bhi.
__device__ __forceinline__ void gemm_chunk(const SmemGemm& s, float acc[4][4][4],
                                           int wm, int wn, int lane) {
  const int qr = lane >> 2;
  const int qc = (lane & 3) << 1;
#pragma unroll
  for (int kk = 0; kk < BK; kk += 16) {
    unsigned ah[4][4], al[4][4], bh[4][2], bl[4][2];
#pragma unroll
    for (int mi = 0; mi < 4; mi++) {
      int r = wm * 64 + mi * 16 + qr;
      ah[mi][0] = *(const unsigned*)&s.a_hi[r][kk + qc];
      ah[mi][1] = *(const unsigned*)&s.a_hi[r + 8][kk + qc];
      ah[mi][2] = *(const unsigned*)&s.a_hi[r][kk + qc + 8];
      ah[mi][3] = *(const unsigned*)&s.a_hi[r + 8][kk + qc + 8];
      al[mi][0] = *(const unsigned*)&s.a_lo[r][kk + qc];
      al[mi][1] = *(const unsigned*)&s.a_lo[r + 8][kk + qc];
      al[mi][2] = *(const unsigned*)&s.a_lo[r][kk + qc + 8];
      al[mi][3] = *(const unsigned*)&s.a_lo[r + 8][kk + qc + 8];
    }
#pragma unroll
    for (int ni = 0; ni < 4; ni++) {
      int c = wn * 32 + ni * 8 + qr;
      bh[ni][0] = *(const unsigned*)&s.b_hi[c][kk + qc];
      bh[ni][1] = *(const unsigned*)&s.b_hi[c][kk + qc + 8];
      bl[ni][0] = *(const unsigned*)&s.b_lo[c][kk + qc];
      bl[ni][1] = *(const unsigned*)&s.b_lo[c][kk + qc + 8];
    }
#pragma unroll
    for (int mi = 0; mi < 4; mi++)
#pragma unroll
      for (int ni = 0; ni < 4; ni++) {
        mma16816(acc[mi][ni], ah[mi], bh[ni]);
        mma16816(acc[mi][ni], ah[mi], bl[ni]);
        mma16816(acc[mi][ni], al[mi], bh[ni]);
      }
  }
}

// Store one 64-row half (phase p) of the accumulator tile into su.ep
__device__ __forceinline__ void store_acc_phase(SmemU& su, float acc[4][4][4],
                                                int wm, int wn, int lane, int p) {
  if (wm == p) {
    const int qr = lane >> 2;
    const int qc = (lane & 3) << 1;
#pragma unroll
    for (int mi = 0; mi < 4; mi++)
#pragma unroll
      for (int ni = 0; ni < 4; ni++) {
        int rr = mi * 16 + qr;
        int cc = wn * 32 + ni * 8 + qc;
        su.ep[rr * 132 + cc] = acc[mi][ni][0];
        su.ep[rr * 132 + cc + 1] = acc[mi][ni][1];
        su.ep[(rr + 8) * 132 + cc] = acc[mi][ni][2];
        su.ep[(rr + 8) * 132 + cc + 1] = acc[mi][ni][3];
      }
  }
}

// ---------------------------------------------------------------------------
// Kernel 1: Xpre[z][l][n][4H] = x[z][n][l][:] @ Wih_z^T + (bih_z + bhh_z)
// grid: (colTile=8, rowTile=1024, z=2), rows indexed r = n*8 + l over [N*L]
// ---------------------------------------------------------------------------
__global__ __launch_bounds__(NTHREADS, 1) void k_precompute(
    const float* __restrict__ xl, const float* __restrict__ xr,
    const float* __restrict__ Wih_l, const float* __restrict__ Wih_r,
    const float* __restrict__ bih_l, const float* __restrict__ bhh_l,
    const float* __restrict__ bih_r, const float* __restrict__ bhh_r) {
  __shared__ SmemU su;
  const int tid = threadIdx.x;
  const int z = blockIdx.z;
  const int colTile = blockIdx.x;
  const long rowBase = (long)blockIdx.y * BM;
  const float* A = z ? xr : xl;
  const float* B = z ? Wih_r : Wih_l;
  const float* bi = z ? bih_r : bih_l;
  const float* bhb = z ? bhh_r : bhh_l;

  const int wid = tid >> 5, lane = tid & 31;
  const int wm = wid & 1, wn = wid >> 1;

  float acc[4][4][4];
#pragma unroll
  for (int a = 0; a < 4; a++)
#pragma unroll
    for (int b = 0; b < 4; b++)
#pragma unroll
      for (int q = 0; q < 4; q++) acc[a][b][q] = 0.0f;

  for (int k0 = 0; k0 < 256; k0 += BK) {
#pragma unroll
    for (int i = 0; i < 4; i++) {
      int f = tid + i * NTHREADS;  // float4 index in 128x32 tile
      int r = f >> 3;
      int c = (f & 7) << 2;
      float4 va = *(const float4*)(A + (rowBase + r) * 256 + k0 + c);
      split4(va, &su.g.a_hi[r][c], &su.g.a_lo[r][c]);
      float4 vb = *(const float4*)(B + (long)(colTile * 128 + r) * 256 + k0 + c);
      split4(vb, &su.g.b_hi[r][c], &su.g.b_lo[r][c]);
    }
    __syncthreads();
    gemm_chunk(su.g, acc, wm, wn, lane);
    __syncthreads();
  }

  for (int p = 0; p < 2; p++) {
    store_acc_phase(su, acc, wm, wn, lane, p);
    __syncthreads();
#pragma unroll
    for (int i = 0; i < 8; i++) {
      int f = tid + i * NTHREADS;  // float4 index in 64x128
      int rl = f >> 5;
      int c4 = (f & 31) << 2;
      float4 v = *(const float4*)&su.ep[rl * 132 + c4];
      int col = colTile * 128 + c4;
      v.x += bi[col] + bhb[col];
      v.y += bi[col + 1] + bhb[col + 1];
      v.z += bi[col + 2] + bhb[col + 2];
      v.w += bi[col + 3] + bhb[col + 3];
      long rg = rowBase + p * 64 + rl;
      long n = rg >> 3;
      int l = (int)(rg & 7);
      *(float4*)(g_X + (((long)z * 8 + l) * 16384 + n) * 1024 + col) = v;
    }
    __syncthreads();
  }
}

// ---------------------------------------------------------------------------
// Kernel 2: step 0 elementwise (h0 = c0 = 0): c = sig(i)*tanh(g); h = sig(o)*tanh(c)
// ---------------------------------------------------------------------------
__global__ void k_step0() {
  long idx = (long)blockIdx.x * 256 + threadIdx.x;  // [0, 2*16384*256)
  long z = idx >> 22;
  long e = idx & 4194303;  // n*256 + j
  long n = e >> 8;
  int j = (int)(e & 255);
  const float* xpre = g_X + z * 8L * 16384 * 1024;
  long xb = n * 1024 + j;
  float gi = xpre[xb];
  float gg = xpre[xb + 512];
  float go = xpre[xb + 768];
  float cn = sigmoidf_(gi) * tanhf(gg);
  g_c[z * 4194304 + e] = cn;
  g_h[(z * 2 + 1) * 4194304 + e] = sigmoidf_(go) * tanhf(cn);
}

// ---------------------------------------------------------------------------
// Kernel 3: recurrent step t (t=1..7): gates = h_{t-1}@Whh^T + Xpre[t]; cell update.
// grid: (strip=8, rowTile=128, z=2). CTA gate-column tile = 4 gates x 32 hidden units.
// h double-buffered: read buf[t&1], write buf[(t+1)&1]; c in place.
// ---------------------------------------------------------------------------
__global__ __launch_bounds__(NTHREADS, 1) void k_step(
    const float* __restrict__ Whh_l, const float* __restrict__ Whh_r, int t) {
  __shared__ SmemU su;
  const int tid = threadIdx.x;
  const int z = blockIdx.z;
  const int strip = blockIdx.x;
  const long rowBase = (long)blockIdx.y * BM;
  const float* B = z ? Whh_r : Whh_l;
  const float* hprev = g_h + ((long)z * 2 + (t & 1)) * 4194304;
  float* hnext = g_h + ((long)z * 2 + ((t + 1) & 1)) * 4194304;
  float* cst = g_c + (long)z * 4194304;
  const float* xpre = g_X + ((long)z * 8 + t) * 16384L * 1024;

  const int wid = tid >> 5, lane = tid & 31;
  const int wm = wid & 1, wn = wid >> 1;

  float acc[4][4][4];
#pragma unroll
  for (int a = 0; a < 4; a++)
#pragma unroll
    for (int b = 0; b < 4; b++)
#pragma unroll
      for (int q = 0; q < 4; q++) acc[a][b][q] = 0.0f;

  for (int k0 = 0; k0 < 256; k0 += BK) {
#pragma unroll
    for (int i = 0; i < 4; i++) {
      int f = tid + i * NTHREADS;
      int r = f >> 3;
      int c = (f & 7) << 2;
      float4 va = *(const float4*)(hprev + (rowBase + r) * 256 + k0 + c);
      split4(va, &su.g.a_hi[r][c], &su.g.a_lo[r][c]);
      // B tile row r -> Whh row = gate*256 + strip*32 + (r&31)
      long brow = (long)((r >> 5) << 8) + strip * 32 + (r & 31);
      float4 vb = *(const float4*)(B + brow * 256 + k0 + c);
      split4(vb, &su.g.b_hi[r][c], &su.g.b_lo[r][c]);
    }
    __syncthreads();
    gemm_chunk(su.g, acc, wm, wn, lane);
    __syncthreads();
  }

  for (int p = 0; p < 2; p++) {
    store_acc_phase(su, acc, wm, wn, lane, p);
    __syncthreads();
#pragma unroll
    for (int i = 0; i < 8; i++) {
      int e = tid + i * NTHREADS;  // 64 rows x 32 hidden units
      int rl = e >> 5;
      int jj = e & 31;
      long n = rowBase + p * 64 + rl;
      int j = strip * 32 + jj;
      long xb = n * 1024 + j;
      float gi = su.ep[rl * 132 + jj] + xpre[xb];
      float gf = su.ep[rl * 132 + 32 + jj] + xpre[xb + 256];
      float gg = su.ep[rl * 132 + 64 + jj] + xpre[xb + 512];
      float go = su.ep[rl * 132 + 96 + jj] + xpre[xb + 768];
      float cn = sigmoidf_(gf) * cst[n * 256 + j] + sigmoidf_(gi) * tanhf(gg);
      cst[n * 256 + j] = cn;
      hnext[n * 256 + j] = sigmoidf_(go) * tanhf(cn);
    }
    __syncthreads();
  }
}

// ---------------------------------------------------------------------------
// Kernel 4: encoder out = tanh([hl, hr, rel] @ Wenc^T + benc)
// grid: (colTile=2, rowTile=128). K = 576 gathered from 3 sources.
// Final h lives in buf 0 for both LSTMs (after t=7 write).
// ---------------------------------------------------------------------------
__global__ __launch_bounds__(NTHREADS, 1) void k_enc(
    const float* __restrict__ rel, const float* __restrict__ Wenc,
    const float* __restrict__ benc, float* __restrict__ out) {
  __shared__ SmemU su;
  const int tid = threadIdx.x;
  const int colTile = blockIdx.x;
  const long rowBase = (long)blockIdx.y * BM;
  const float* hL = g_h;                   // z=0, buf 0
  const float* hR = g_h + 2L * 4194304;    // z=1, buf 0

  const int wid = tid >> 5, lane = tid & 31;
  const int wm = wid & 1, wn = wid >> 1;

  float acc[4][4][4];
#pragma unroll
  for (int a = 0; a < 4; a++)
#pragma unroll
    for (int b = 0; b < 4; b++)
#pragma unroll
      for (int q = 0; q < 4; q++) acc[a][b][q] = 0.0f;

  for (int k0 = 0; k0 < 576; k0 += BK) {
    const float* Asrc;
    long lda, koff;
    if (k0 < 256) {
      Asrc = hL; lda = 256; koff = k0;
    } else if (k0 < 512) {
      Asrc = hR; lda = 256; koff = k0 - 256;
    } else {
      Asrc = rel; lda = 64; koff = k0 - 512;
    }
#pragma unroll
    for (int i = 0; i < 4; i++) {
      int f = tid + i * NTHREADS;
      int r = f >> 3;
      int c = (f & 7) << 2;
      float4 va = *(const float4*)(Asrc + (rowBase + r) * lda + koff + c);
      split4(va, &su.g.a_hi[r][c], &su.g.a_lo[r][c]);
      float4 vb = *(const float4*)(Wenc + (long)(colTile * 128 + r) * 576 + k0 + c);
      split4(vb, &su.g.b_hi[r][c], &su.g.b_lo[r][c]);
    }
    __syncthreads();
    gemm_chunk(su.g, acc, wm, wn, lane);
    __syncthreads();
  }

  for (int p = 0; p < 2; p++) {
    store_acc_phase(su, acc, wm, wn, lane, p);
    __syncthreads();
#pragma unroll
    for (int i = 0; i < 8; i++) {
      int f = tid + i * NTHREADS;
      int rl = f >> 5;
      int c4 = (f & 31) << 2;
      float4 v = *(const float4*)&su.ep[rl * 132 + c4];
      int col = colTile * 128 + c4;
      v.x = tanhf(v.x + benc[col]);
      v.y = tanhf(v.y + benc[col + 1]);
      v.z = tanhf(v.z + benc[col + 2]);
      v.w = tanhf(v.w + benc[col + 3]);
      long n = rowBase + p * 64 + rl;
      *(float4*)(out + n * 256 + col) = v;
    }
    __syncthreads();
  }
}

// ---------------------------------------------------------------------------
extern "C" void kernel_launch(void* const* d_in, const int* in_sizes, int n_in,
                              void* d_out, int out_size) {
  (void)in_sizes; (void)n_in; (void)out_size;
  const float* left  = (const float*)d_in[0];
  const float* right = (const float*)d_in[1];
  const float* rel   = (const float*)d_in[2];
  const float* Wih_l = (const float*)d_in[3];
  const float* Whh_l = (const float*)d_in[4];
  const float* bih_l = (const float*)d_in[5];
  const float* bhh_l = (const float*)d_in[6];
  const float* Wih_r = (const float*)d_in[7];
  const float* Whh_r = (const float*)d_in[8];
  const float* bih_r = (const float*)d_in[9];
  const float* bhh_r = (const float*)d_in[10];
  const float* Wenc  = (const float*)d_in[11];
  const float* benc  = (const float*)d_in[12];
  float* out = (float*)d_out;

  k_precompute<<<dim3(8, 1024, 2), NTHREADS>>>(left, right, Wih_l, Wih_r,
                                               bih_l, bhh_l, bih_r, bhh_r);
  k_step0<<<32768, 256>>>();
  for (int t = 1; t < 8; t++)
    k_step<<<dim3(8, 128, 2), NTHREADS>>>(Whh_l, Whh_r, t);
  k_enc<<<dim3(2, 128), NTHREADS>>>(rel, Wenc, benc, out);
}

// round 7
// speedup vs baseline: 1.0151x; 1.0151x over previous
#include <cuda_runtime.h>
#include <cuda_bf16.h>
#include <math.h>

// Problem constants
// N=16384 nodes, L=8 chain, D=256 in, H=256 hidden, R=64 rel
// Gate order (PyTorch): i, f, g, o

#define NTHREADS 256
#define BM 128
#define BN 128
#define BK 32

// Scratch (device globals — allocation-free rule)
__device__ float g_X[268435456];  // [2][8][16384][1024] : Xpre = x@Wih^T + (bih+bhh)
__device__ float g_h[16777216];   // [2 lstm][2 buf][16384][256]
__device__ float g_c[8388608];    // [2 lstm][16384][256]

struct SmemGemm {
  __nv_bfloat16 a_hi[BM][BK + 2];
  __nv_bfloat16 a_lo[BM][BK + 2];
  __nv_bfloat16 b_hi[BN][BK + 2];
  __nv_bfloat16 b_lo[BN][BK + 2];
};
union SmemU {
  SmemGemm g;
  float ep[64 * 132];  // epilogue half-tile (64 rows x 128 cols, padded stride 132)
};

__device__ __forceinline__ void mma16816(float* d, const unsigned* a, const unsigned* b) {
  asm volatile(
      "mma.sync.aligned.m16n8k16.row.col.f32.bf16.bf16.f32 "
      "{%0,%1,%2,%3}, {%4,%5,%6,%7}, {%8,%9}, {%0,%1,%2,%3};\n"
      : "+f"(d[0]), "+f"(d[1]), "+f"(d[2]), "+f"(d[3])
      : "r"(a[0]), "r"(a[1]), "r"(a[2]), "r"(a[3]), "r"(b[0]), "r"(b[1]));
}

// fp32 -> (hi, lo) bf16 split; 3 cross-products recover ~16-bit mantissa accuracy
__device__ __forceinline__ void split4(float4 v, __nv_bfloat16* hi, __nv_bfloat16* lo) {
  float x[4] = {v.x, v.y, v.z, v.w};
#pragma unroll
  for (int q = 0; q < 4; q++) {
    __nv_bfloat16 h = __float2bfloat16(x[q]);
    hi[q] = h;
    lo[q] = __float2bfloat16(x[q] - __bfloat162float(h));
  }
}

__device__ __forceinline__ float sigmoidf_(float x) { return 1.0f / (1.0f + expf(-x)); }

// One BK-chunk of the 128x128 warp-tiled GEMM (8 warps: wm in {0,1} x wn in {0..3};
// warp tile 64x32 = 4x4 m16n8 fragments). acc += Ahi*Bhi + Ahi*Blo + Alo*Bhi.
__device__ __forceinline__ void gemm_chunk(const SmemGemm& s, float acc[4][4][4],
                                           int wm, int wn, int lane) {
  const int qr = lane >> 2;
  const int qc = (lane & 3) << 1;
#pragma unroll
  for (int kk = 0; kk < BK; kk += 16) {
    unsigned ah[4][4], al[4][4], bh[4][2], bl[4][2];
#pragma unroll
    for (int mi = 0; mi < 4; mi++) {
      int r = wm * 64 + mi * 16 + qr;
      ah[mi][0] = *(const unsigned*)&s.a_hi[r][kk + qc];
      ah[mi][1] = *(const unsigned*)&s.a_hi[r + 8][kk + qc];
      ah[mi][2] = *(const unsigned*)&s.a_hi[r][kk + qc + 8];
      ah[mi][3] = *(const unsigned*)&s.a_hi[r + 8][kk + qc + 8];
      al[mi][0] = *(const unsigned*)&s.a_lo[r][kk + qc];
      al[mi][1] = *(const unsigned*)&s.a_lo[r + 8][kk + qc];
      al[mi][2] = *(const unsigned*)&s.a_lo[r][kk + qc + 8];
      al[mi][3] = *(const unsigned*)&s.a_lo[r + 8][kk + qc + 8];
    }
#pragma unroll
    for (int ni = 0; ni < 4; ni++) {
      int c = wn * 32 + ni * 8 + qr;
      bh[ni][0] = *(const unsigned*)&s.b_hi[c][kk + qc];
      bh[ni][1] = *(const unsigned*)&s.b_hi[c][kk + qc + 8];
      bl[ni][0] = *(const unsigned*)&s.b_lo[c][kk + qc];
      bl[ni][1] = *(const unsigned*)&s.b_lo[c][kk + qc + 8];
    }
#pragma unroll
    for (int mi = 0; mi < 4; mi++)
#pragma unroll
      for (int ni = 0; ni < 4; ni++) {
        mma16816(acc[mi][ni], ah[mi], bh[ni]);
        mma16816(acc[mi][ni], ah[mi], bl[ni]);
        mma16816(acc[mi][ni], al[mi], bh[ni]);
      }
  }
}

// Store one 64-row half (phase p) of the accumulator tile into su.ep
__device__ __forceinline__ void store_acc_phase(SmemU& su, float acc[4][4][4],
                                                int wm, int wn, int lane, int p) {
  if (wm == p) {
    const int qr = lane >> 2;
    const int qc = (lane & 3) << 1;
#pragma unroll
    for (int mi = 0; mi < 4; mi++)
#pragma unroll
      for (int ni = 0; ni < 4; ni++) {
        int rr = mi * 16 + qr;
        int cc = wn * 32 + ni * 8 + qc;
        su.ep[rr * 132 + cc] = acc[mi][ni][0];
        su.ep[rr * 132 + cc + 1] = acc[mi][ni][1];
        su.ep[(rr + 8) * 132 + cc] = acc[mi][ni][2];
        su.ep[(rr + 8) * 132 + cc + 1] = acc[mi][ni][3];
      }
  }
}

// ---------------------------------------------------------------------------
// Kernel 1: Xpre[z][l][n][4H] = x[z][n][l][:] @ Wih_z^T + (bih_z + bhh_z)
// grid: (colTile=8, rowTile=1024, z=2), rows indexed r = n*8 + l over [N*L]
// ---------------------------------------------------------------------------
__global__ __launch_bounds__(NTHREADS, 1) void k_precompute(
    const float* __restrict__ xl, const float* __restrict__ xr,
    const float* __restrict__ Wih_l, const float* __restrict__ Wih_r,
    const float* __restrict__ bih_l, const float* __restrict__ bhh_l,
    const float* __restrict__ bih_r, const float* __restrict__ bhh_r) {
  __shared__ SmemU su;
  const int tid = threadIdx.x;
  const int z = blockIdx.z;
  const int colTile = blockIdx.x;
  const long rowBase = (long)blockIdx.y * BM;
  const float* A = z ? xr : xl;
  const float* B = z ? Wih_r : Wih_l;
  const float* bi = z ? bih_r : bih_l;
  const float* bhb = z ? bhh_r : bhh_l;

  const int wid = tid >> 5, lane = tid & 31;
  const int wm = wid & 1, wn = wid >> 1;

  float acc[4][4][4];
#pragma unroll
  for (int a = 0; a < 4; a++)
#pragma unroll
    for (int b = 0; b < 4; b++)
#pragma unroll
      for (int q = 0; q < 4; q++) acc[a][b][q] = 0.0f;

  for (int k0 = 0; k0 < 256; k0 += BK) {
#pragma unroll
    for (int i = 0; i < 4; i++) {
      int f = tid + i * NTHREADS;  // float4 index in 128x32 tile
      int r = f >> 3;
      int c = (f & 7) << 2;
      float4 va = *(const float4*)(A + (rowBase + r) * 256 + k0 + c);
      split4(va, &su.g.a_hi[r][c], &su.g.a_lo[r][c]);
      float4 vb = *(const float4*)(B + (long)(colTile * 128 + r) * 256 + k0 + c);
      split4(vb, &su.g.b_hi[r][c], &su.g.b_lo[r][c]);
    }
    __syncthreads();
    gemm_chunk(su.g, acc, wm, wn, lane);
    __syncthreads();
  }

  for (int p = 0; p < 2; p++) {
    store_acc_phase(su, acc, wm, wn, lane, p);
    __syncthreads();
#pragma unroll
    for (int i = 0; i < 8; i++) {
      int f = tid + i * NTHREADS;  // float4 index in 64x128
      int rl = f >> 5;
      int c4 = (f & 31) << 2;
      float4 v = *(const float4*)&su.ep[rl * 132 + c4];
      int col = colTile * 128 + c4;
      v.x += bi[col] + bhb[col];
      v.y += bi[col + 1] + bhb[col + 1];
      v.z += bi[col + 2] + bhb[col + 2];
      v.w += bi[col + 3] + bhb[col + 3];
      long rg = rowBase + p * 64 + rl;
      long n = rg >> 3;
      int l = (int)(rg & 7);
      *(float4*)(g_X + (((long)z * 8 + l) * 16384 + n) * 1024 + col) = v;
    }
    __syncthreads();
  }
}

// ---------------------------------------------------------------------------
// Kernel 2: step 0 elementwise (h0 = c0 = 0): c = sig(i)*tanh(g); h = sig(o)*tanh(c)
// ---------------------------------------------------------------------------
__global__ void k_step0() {
  long idx = (long)blockIdx.x * 256 + threadIdx.x;  // [0, 2*16384*256)
  long z = idx >> 22;
  long e = idx & 4194303;  // n*256 + j
  long n = e >> 8;
  int j = (int)(e & 255);
  const float* xpre = g_X + z * 8L * 16384 * 1024;
  long xb = n * 1024 + j;
  float gi = xpre[xb];
  float gg = xpre[xb + 512];
  float go = xpre[xb + 768];
  float cn = sigmoidf_(gi) * tanhf(gg);
  g_c[z * 4194304 + e] = cn;
  g_h[(z * 2 + 1) * 4194304 + e] = sigmoidf_(go) * tanhf(cn);
}

// ---------------------------------------------------------------------------
// Kernel 3: recurrent step t (t=1..7): gates = h_{t-1}@Whh^T + Xpre[t]; cell update.
// grid: (strip=8, rowTile=128, z=2). CTA gate-column tile = 4 gates x 32 hidden units.
// h double-buffered: read buf[t&1], write buf[(t+1)&1]; c in place.
// ---------------------------------------------------------------------------
__global__ __launch_bounds__(NTHREADS, 1) void k_step(
    const float* __restrict__ Whh_l, const float* __restrict__ Whh_r, int t) {
  __shared__ SmemU su;
  const int tid = threadIdx.x;
  const int z = blockIdx.z;
  const int strip = blockIdx.x;
  const long rowBase = (long)blockIdx.y * BM;
  const float* B = z ? Whh_r : Whh_l;
  const float* hprev = g_h + ((long)z * 2 + (t & 1)) * 4194304;
  float* hnext = g_h + ((long)z * 2 + ((t + 1) & 1)) * 4194304;
  float* cst = g_c + (long)z * 4194304;
  const float* xpre = g_X + ((long)z * 8 + t) * 16384L * 1024;

  const int wid = tid >> 5, lane = tid & 31;
  const int wm = wid & 1, wn = wid >> 1;

  float acc[4][4][4];
#pragma unroll
  for (int a = 0; a < 4; a++)
#pragma unroll
    for (int b = 0; b < 4; b++)
#pragma unroll
      for (int q = 0; q < 4; q++) acc[a][b][q] = 0.0f;

  for (int k0 = 0; k0 < 256; k0 += BK) {
#pragma unroll
    for (int i = 0; i < 4; i++) {
      int f = tid + i * NTHREADS;
      int r = f >> 3;
      int c = (f & 7) << 2;
      float4 va = *(const float4*)(hprev + (rowBase + r) * 256 + k0 + c);
      split4(va, &su.g.a_hi[r][c], &su.g.a_lo[r][c]);
      // B tile row r -> Whh row = gate*256 + strip*32 + (r&31)
      long brow = (long)((r >> 5) << 8) + strip * 32 + (r & 31);
      float4 vb = *(const float4*)(B + brow * 256 + k0 + c);
      split4(vb, &su.g.b_hi[r][c], &su.g.b_lo[r][c]);
    }
    __syncthreads();
    gemm_chunk(su.g, acc, wm, wn, lane);
    __syncthreads();
  }

  for (int p = 0; p < 2; p++) {
    store_acc_phase(su, acc, wm, wn, lane, p);
    __syncthreads();
#pragma unroll
    for (int i = 0; i < 8; i++) {
      int e = tid + i * NTHREADS;  // 64 rows x 32 hidden units
      int rl = e >> 5;
      int jj = e & 31;
      long n = rowBase + p * 64 + rl;
      int j = strip * 32 + jj;
      long xb = n * 1024 + j;
      float gi = su.ep[rl * 132 + jj] + xpre[xb];
      float gf = su.ep[rl * 132 + 32 + jj] + xpre[xb + 256];
      float gg = su.ep[rl * 132 + 64 + jj] + xpre[xb + 512];
      float go = su.ep[rl * 132 + 96 + jj] + xpre[xb + 768];
      float cn = sigmoidf_(gf) * cst[n * 256 + j] + sigmoidf_(gi) * tanhf(gg);
      cst[n * 256 + j] = cn;
      hnext[n * 256 + j] = sigmoidf_(go) * tanhf(cn);
    }
    __syncthreads();
  }
}

// ---------------------------------------------------------------------------
// Kernel 4: encoder out = tanh([hl, hr, rel] @ Wenc^T + benc)
// grid: (colTile=2, rowTile=128). K = 576 gathered from 3 sources.
// Final h lives in buf 0 for both LSTMs (after t=7 write).
// ---------------------------------------------------------------------------
__global__ __launch_bounds__(NTHREADS, 1) void k_enc(
    const float* __restrict__ rel, const float* __restrict__ Wenc,
    const float* __restrict__ benc, float* __restrict__ out) {
  __shared__ SmemU su;
  const int tid = threadIdx.x;
  const int colTile = blockIdx.x;
  const long rowBase = (long)blockIdx.y * BM;
  const float* hL = g_h;                   // z=0, buf 0
  const float* hR = g_h + 2L * 4194304;    // z=1, buf 0

  const int wid = tid >> 5, lane = tid & 31;
  const int wm = wid & 1, wn = wid >> 1;

  float acc[4][4][4];
#pragma unroll
  for (int a = 0; a < 4; a++)
#pragma unroll
    for (int b = 0; b < 4; b++)
#pragma unroll
      for (int q = 0; q < 4; q++) acc[a][b][q] = 0.0f;

  for (int k0 = 0; k0 < 576; k0 += BK) {
    const float* Asrc;
    long lda, koff;
    if (k0 < 256) {
      Asrc = hL; lda = 256; koff = k0;
    } else if (k0 < 512) {
      Asrc = hR; lda = 256; koff = k0 - 256;
    } else {
      Asrc = rel; lda = 64; koff = k0 - 512;
    }
#pragma unroll
    for (int i = 0; i < 4; i++) {
      int f = tid + i * NTHREADS;
      int r = f >> 3;
      int c = (f & 7) << 2;
      float4 va = *(const float4*)(Asrc + (rowBase + r) * lda + koff + c);
      split4(va, &su.g.a_hi[r][c], &su.g.a_lo[r][c]);
      float4 vb = *(const float4*)(Wenc + (long)(colTile * 128 + r) * 576 + k0 + c);
      split4(vb, &su.g.b_hi[r][c], &su.g.b_lo[r][c]);
    }
    __syncthreads();
    gemm_chunk(su.g, acc, wm, wn, lane);
    __syncthreads();
  }

  for (int p = 0; p < 2; p++) {
    store_acc_phase(su, acc, wm, wn, lane, p);
    __syncthreads();
#pragma unroll
    for (int i = 0; i < 8; i++) {
      int f = tid + i * NTHREADS;
      int rl = f >> 5;
      int c4 = (f & 31) << 2;
      float4 v = *(const float4*)&su.ep[rl * 132 + c4];
      int col = colTile * 128 + c4;
      v.x = tanhf(v.x + benc[col]);
      v.y = tanhf(v.y + benc[col + 1]);
      v.z = tanhf(v.z + benc[col + 2]);
      v.w = tanhf(v.w + benc[col + 3]);
      long n = rowBase + p * 64 + rl;
      *(float4*)(out + n * 256 + col) = v;
    }
    __syncthreads();
  }
}

// ---------------------------------------------------------------------------
extern "C" void kernel_launch(void* const* d_in, const int* in_sizes, int n_in,
                              void* d_out, int out_size) {
  (void)in_sizes; (void)n_in; (void)out_size;
  const float* left  = (const float*)d_in[0];
  const float* right = (const float*)d_in[1];
  const float* rel   = (const float*)d_in[2];
  const float* Wih_l = (const float*)d_in[3];
  const float* Whh_l = (const float*)d_in[4];
  const float* bih_l = (const float*)d_in[5];
  const float* bhh_l = (const float*)d_in[6];
  const float* Wih_r = (const float*)d_in[7];
  const float* Whh_r = (const float*)d_in[8];
  const float* bih_r = (const float*)d_in[9];
  const float* bhh_r = (const float*)d_in[10];
  const float* Wenc  = (const float*)d_in[11];
  const float* benc  = (const float*)d_in[12];
  float* out = (float*)d_out;

  k_precompute<<<dim3(8, 1024, 2), NTHREADS>>>(left, right, Wih_l, Wih_r,
                                               bih_l, bhh_l, bih_r, bhh_r);
  k_step0<<<32768, 256>>>();
  for (int t = 1; t < 8; t++)
    k_step<<<dim3(8, 128, 2), NTHREADS>>>(Whh_l, Whh_r, t);
  k_enc<<<dim3(2, 128), NTHREADS>>>(rel, Wenc, benc, out);
}

// round 8
// speedup vs baseline: 1.0157x; 1.0005x over previous
#include <cuda_runtime.h>
#include <cuda_bf16.h>
#include <math.h>

// Problem constants
// N=16384 nodes, L=8 chain, D=256 in, H=256 hidden, R=64 rel
// Gate order (PyTorch): i, f, g, o

#define NTHREADS 256
#define BM 128
#define BN 128
#define BK 32

// Scratch (device globals — allocation-free rule)
__device__ float g_X[268435456];  // [2][8][16384][1024] : Xpre = x@Wih^T + (bih+bhh)
__device__ float g_h[16777216];   // [2 lstm][2 buf][16384][256]
__device__ float g_c[8388608];    // [2 lstm][16384][256]

struct SmemGemm {
  __nv_bfloat16 a_hi[BM][BK + 2];
  __nv_bfloat16 a_lo[BM][BK + 2];
  __nv_bfloat16 b_hi[BN][BK + 2];
  __nv_bfloat16 b_lo[BN][BK + 2];
};
union SmemU {
  SmemGemm g;
  float ep[64 * 132];  // epilogue half-tile (64 rows x 128 cols, padded stride 132)
};

__device__ __forceinline__ void mma16816(float* d, const unsigned* a, const unsigned* b) {
  asm volatile(
      "mma.sync.aligned.m16n8k16.row.col.f32.bf16.bf16.f32 "
      "{%0,%1,%2,%3}, {%4,%5,%6,%7}, {%8,%9}, {%0,%1,%2,%3};\n"
      : "+f"(d[0]), "+f"(d[1]), "+f"(d[2]), "+f"(d[3])
      : "r"(a[0]), "r"(a[1]), "r"(a[2]), "r"(a[3]), "r"(b[0]), "r"(b[1]));
}

// fp32 -> (hi, lo) bf16 split; 3 cross-products recover ~16-bit mantissa accuracy
__device__ __forceinline__ void split4(float4 v, __nv_bfloat16* hi, __nv_bfloat16* lo) {
  float x[4] = {v.x, v.y, v.z, v.w};
#pragma unroll
  for (int q = 0; q < 4; q++) {
    __nv_bfloat16 h = __float2bfloat16(x[q]);
    hi[q] = h;
    lo[q] = __float2bfloat16(x[q] - __bfloat162float(h));
  }
}

__device__ __forceinline__ float sigmoidf_(float x) { return 1.0f / (1.0f + expf(-x)); }

// One BK-chunk of the 128x128 warp-tiled GEMM (8 warps: wm in {0,1} x wn in {0..3};
// warp tile 64x32 = 4x4 m16n8 fragments). acc += Ahi*Bhi + Ahi*Blo + Alo*Bhi.
__device__ __forceinline__ void gemm_chunk(const SmemGemm& s, float acc[4][4][4],
                                           int wm, int wn, int lane) {
  const int qr = lane >> 2;
  const int qc = (lane & 3) << 1;
#pragma unroll
  for (int kk = 0; kk < BK; kk += 16) {
    unsigned ah[4][4], al[4][4], bh[4][2], bl[4][2];
#pragma unroll
    for (int mi = 0; mi < 4; mi++) {
      int r = wm * 64 + mi * 16 + qr;
      ah[mi][0] = *(const unsigned*)&s.a_hi[r][kk + qc];
      ah[mi][1] = *(const unsigned*)&s.a_hi[r + 8][kk + qc];
      ah[mi][2] = *(const unsigned*)&s.a_hi[r][kk + qc + 8];
      ah[mi][3] = *(const unsigned*)&s.a_hi[r + 8][kk + qc + 8];
      al[mi][0] = *(const unsigned*)&s.a_lo[r][kk + qc];
      al[mi][1] = *(const unsigned*)&s.a_lo[r + 8][kk + qc];
      al[mi][2] = *(const unsigned*)&s.a_lo[r][kk + qc + 8];
      al[mi][3] = *(const unsigned*)&s.a_lo[r + 8][kk + qc + 8];
    }
#pragma unroll
    for (int ni = 0; ni < 4; ni++) {
      int c = wn * 32 + ni * 8 + qr;
      bh[ni][0] = *(const unsigned*)&s.b_hi[c][kk + qc];
      bh[ni][1] = *(const unsigned*)&s.b_hi[c][kk + qc + 8];
      bl[ni][0] = *(const unsigned*)&s.b_lo[c][kk + qc];
      bl[ni][1] = *(const unsigned*)&s.b_lo[c][kk + qc + 8];
    }
#pragma unroll
    for (int mi = 0; mi < 4; mi++)
#pragma unroll
      for (int ni = 0; ni < 4; ni++) {
        mma16816(acc[mi][ni], ah[mi], bh[ni]);
        mma16816(acc[mi][ni], ah[mi], bl[ni]);
        mma16816(acc[mi][ni], al[mi], bh[ni]);
      }
  }
}

// Store one 64-row half (phase p) of the accumulator tile into su.ep
__device__ __forceinline__ void store_acc_phase(SmemU& su, float acc[4][4][4],
                                                int wm, int wn, int lane, int p) {
  if (wm == p) {
    const int qr = lane >> 2;
    const int qc = (lane & 3) << 1;
#pragma unroll
    for (int mi = 0; mi < 4; mi++)
#pragma unroll
      for (int ni = 0; ni < 4; ni++) {
        int rr = mi * 16 + qr;
        int cc = wn * 32 + ni * 8 + qc;
        su.ep[rr * 132 + cc] = acc[mi][ni][0];
        su.ep[rr * 132 + cc + 1] = acc[mi][ni][1];
        su.ep[(rr + 8) * 132 + cc] = acc[mi][ni][2];
        su.ep[(rr + 8) * 132 + cc + 1] = acc[mi][ni][3];
      }
  }
}

// ---------------------------------------------------------------------------
// Kernel 1: Xpre[z][l][n][4H] = x[z][n][l][:] @ Wih_z^T + (bih_z + bhh_z)
// grid: (colTile=8, rowTile=1024, z=2), rows indexed r = n*8 + l over [N*L]
// ---------------------------------------------------------------------------
__global__ __launch_bounds__(NTHREADS, 1) void k_precompute(
    const float* __restrict__ xl, const float* __restrict__ xr,
    const float* __restrict__ Wih_l, const float* __restrict__ Wih_r,
    const float* __restrict__ bih_l, const float* __restrict__ bhh_l,
    const float* __restrict__ bih_r, const float* __restrict__ bhh_r) {
  __shared__ SmemU su;
  const int tid = threadIdx.x;
  const int z = blockIdx.z;
  const int colTile = blockIdx.x;
  const long rowBase = (long)blockIdx.y * BM;
  const float* A = z ? xr : xl;
  const float* B = z ? Wih_r : Wih_l;
  const float* bi = z ? bih_r : bih_l;
  const float* bhb = z ? bhh_r : bhh_l;

  const int wid = tid >> 5, lane = tid & 31;
  const int wm = wid & 1, wn = wid >> 1;

  float acc[4][4][4];
#pragma unroll
  for (int a = 0; a < 4; a++)
#pragma unroll
    for (int b = 0; b < 4; b++)
#pragma unroll
      for (int q = 0; q < 4; q++) acc[a][b][q] = 0.0f;

  for (int k0 = 0; k0 < 256; k0 += BK) {
#pragma unroll
    for (int i = 0; i < 4; i++) {
      int f = tid + i * NTHREADS;  // float4 index in 128x32 tile
      int r = f >> 3;
      int c = (f & 7) << 2;
      float4 va = *(const float4*)(A + (rowBase + r) * 256 + k0 + c);
      split4(va, &su.g.a_hi[r][c], &su.g.a_lo[r][c]);
      float4 vb = *(const float4*)(B + (long)(colTile * 128 + r) * 256 + k0 + c);
      split4(vb, &su.g.b_hi[r][c], &su.g.b_lo[r][c]);
    }
    __syncthreads();
    gemm_chunk(su.g, acc, wm, wn, lane);
    __syncthreads();
  }

  for (int p = 0; p < 2; p++) {
    store_acc_phase(su, acc, wm, wn, lane, p);
    __syncthreads();
#pragma unroll
    for (int i = 0; i < 8; i++) {
      int f = tid + i * NTHREADS;  // float4 index in 64x128
      int rl = f >> 5;
      int c4 = (f & 31) << 2;
      float4 v = *(const float4*)&su.ep[rl * 132 + c4];
      int col = colTile * 128 + c4;
      v.x += bi[col] + bhb[col];
      v.y += bi[col + 1] + bhb[col + 1];
      v.z += bi[col + 2] + bhb[col + 2];
      v.w += bi[col + 3] + bhb[col + 3];
      long rg = rowBase + p * 64 + rl;
      long n = rg >> 3;
      int l = (int)(rg & 7);
      *(float4*)(g_X + (((long)z * 8 + l) * 16384 + n) * 1024 + col) = v;
    }
    __syncthreads();
  }
}

// ---------------------------------------------------------------------------
// Kernel 2: step 0 elementwise (h0 = c0 = 0): c = sig(i)*tanh(g); h = sig(o)*tanh(c)
// ---------------------------------------------------------------------------
__global__ void k_step0() {
  long idx = (long)blockIdx.x * 256 + threadIdx.x;  // [0, 2*16384*256)
  long z = idx >> 22;
  long e = idx & 4194303;  // n*256 + j
  long n = e >> 8;
  int j = (int)(e & 255);
  const float* xpre = g_X + z * 8L * 16384 * 1024;
  long xb = n * 1024 + j;
  float gi = xpre[xb];
  float gg = xpre[xb + 512];
  float go = xpre[xb + 768];
  float cn = sigmoidf_(gi) * tanhf(gg);
  g_c[z * 4194304 + e] = cn;
  g_h[(z * 2 + 1) * 4194304 + e] = sigmoidf_(go) * tanhf(cn);
}

// ---------------------------------------------------------------------------
// Kernel 3: recurrent step t (t=1..7): gates = h_{t-1}@Whh^T + Xpre[t]; cell update.
// grid: (strip=8, rowTile=128, z=2). CTA gate-column tile = 4 gates x 32 hidden units.
// h double-buffered: read buf[t&1], write buf[(t+1)&1]; c in place.
// ---------------------------------------------------------------------------
__global__ __launch_bounds__(NTHREADS, 1) void k_step(
    const float* __restrict__ Whh_l, const float* __restrict__ Whh_r, int t) {
  __shared__ SmemU su;
  const int tid = threadIdx.x;
  const int z = blockIdx.z;
  const int strip = blockIdx.x;
  const long rowBase = (long)blockIdx.y * BM;
  const float* B = z ? Whh_r : Whh_l;
  const float* hprev = g_h + ((long)z * 2 + (t & 1)) * 4194304;
  float* hnext = g_h + ((long)z * 2 + ((t + 1) & 1)) * 4194304;
  float* cst = g_c + (long)z * 4194304;
  const float* xpre = g_X + ((long)z * 8 + t) * 16384L * 1024;

  const int wid = tid >> 5, lane = tid & 31;
  const int wm = wid & 1, wn = wid >> 1;

  float acc[4][4][4];
#pragma unroll
  for (int a = 0; a < 4; a++)
#pragma unroll
    for (int b = 0; b < 4; b++)
#pragma unroll
      for (int q = 0; q < 4; q++) acc[a][b][q] = 0.0f;

  for (int k0 = 0; k0 < 256; k0 += BK) {
#pragma unroll
    for (int i = 0; i < 4; i++) {
      int f = tid + i * NTHREADS;
      int r = f >> 3;
      int c = (f & 7) << 2;
      float4 va = *(const float4*)(hprev + (rowBase + r) * 256 + k0 + c);
      split4(va, &su.g.a_hi[r][c], &su.g.a_lo[r][c]);
      // B tile row r -> Whh row = gate*256 + strip*32 + (r&31)
      long brow = (long)((r >> 5) << 8) + strip * 32 + (r & 31);
      float4 vb = *(const float4*)(B + brow * 256 + k0 + c);
      split4(vb, &su.g.b_hi[r][c], &su.g.b_lo[r][c]);
    }
    __syncthreads();
    gemm_chunk(su.g, acc, wm, wn, lane);
    __syncthreads();
  }

  for (int p = 0; p < 2; p++) {
    store_acc_phase(su, acc, wm, wn, lane, p);
    __syncthreads();
#pragma unroll
    for (int i = 0; i < 8; i++) {
      int e = tid + i * NTHREADS;  // 64 rows x 32 hidden units
      int rl = e >> 5;
      int jj = e & 31;
      long n = rowBase + p * 64 + rl;
      int j = strip * 32 + jj;
      long xb = n * 1024 + j;
      float gi = su.ep[rl * 132 + jj] + xpre[xb];
      float gf = su.ep[rl * 132 + 32 + jj] + xpre[xb + 256];
      float gg = su.ep[rl * 132 + 64 + jj] + xpre[xb + 512];
      float go = su.ep[rl * 132 + 96 + jj] + xpre[xb + 768];
      float cn = sigmoidf_(gf) * cst[n * 256 + j] + sigmoidf_(gi) * tanhf(gg);
      cst[n * 256 + j] = cn;
      hnext[n * 256 + j] = sigmoidf_(go) * tanhf(cn);
    }
    __syncthreads();
  }
}

// ---------------------------------------------------------------------------
// Kernel 4: encoder out = tanh([hl, hr, rel] @ Wenc^T + benc)
// grid: (colTile=2, rowTile=128). K = 576 gathered from 3 sources.
// Final h lives in buf 0 for both LSTMs (after t=7 write).
// ---------------------------------------------------------------------------
__global__ __launch_bounds__(NTHREADS, 1) void k_enc(
    const float* __restrict__ rel, const float* __restrict__ Wenc,
    const float* __restrict__ benc, float* __restrict__ out) {
  __shared__ SmemU su;
  const int tid = threadIdx.x;
  const int colTile = blockIdx.x;
  const long rowBase = (long)blockIdx.y * BM;
  const float* hL = g_h;                   // z=0, buf 0
  const float* hR = g_h + 2L * 4194304;    // z=1, buf 0

  const int wid = tid >> 5, lane = tid & 31;
  const int wm = wid & 1, wn = wid >> 1;

  float acc[4][4][4];
#pragma unroll
  for (int a = 0; a < 4; a++)
#pragma unroll
    for (int b = 0; b < 4; b++)
#pragma unroll
      for (int q = 0; q < 4; q++) acc[a][b][q] = 0.0f;

  for (int k0 = 0; k0 < 576; k0 += BK) {
    const float* Asrc;
    long lda, koff;
    if (k0 < 256) {
      Asrc = hL; lda = 256; koff = k0;
    } else if (k0 < 512) {
      Asrc = hR; lda = 256; koff = k0 - 256;
    } else {
      Asrc = rel; lda = 64; koff = k0 - 512;
    }
#pragma unroll
    for (int i = 0; i < 4; i++) {
      int f = tid + i * NTHREADS;
      int r = f >> 3;
      int c = (f & 7) << 2;
      float4 va = *(const float4*)(Asrc + (rowBase + r) * lda + koff + c);
      split4(va, &su.g.a_hi[r][c], &su.g.a_lo[r][c]);
      float4 vb = *(const float4*)(Wenc + (long)(colTile * 128 + r) * 576 + k0 + c);
      split4(vb, &su.g.b_hi[r][c], &su.g.b_lo[r][c]);
    }
    __syncthreads();
    gemm_chunk(su.g, acc, wm, wn, lane);
    __syncthreads();
  }

  for (int p = 0; p < 2; p++) {
    store_acc_phase(su, acc, wm, wn, lane, p);
    __syncthreads();
#pragma unroll
    for (int i = 0; i < 8; i++) {
      int f = tid + i * NTHREADS;
      int rl = f >> 5;
      int c4 = (f & 31) << 2;
      float4 v = *(const float4*)&su.ep[rl * 132 + c4];
      int col = colTile * 128 + c4;
      v.x = tanhf(v.x + benc[col]);
      v.y = tanhf(v.y + benc[col + 1]);
      v.z = tanhf(v.z + benc[col + 2]);
      v.w = tanhf(v.w + benc[col + 3]);
      long n = rowBase + p * 64 + rl;
      *(float4*)(out + n * 256 + col) = v;
    }
    __syncthreads();
  }
}

// ---------------------------------------------------------------------------
extern "C" void kernel_launch(void* const* d_in, const int* in_sizes, int n_in,
                              void* d_out, int out_size) {
  (void)in_sizes; (void)n_in; (void)out_size;
  const float* left  = (const float*)d_in[0];
  const float* right = (const float*)d_in[1];
  const float* rel   = (const float*)d_in[2];
  const float* Wih_l = (const float*)d_in[3];
  const float* Whh_l = (const float*)d_in[4];
  const float* bih_l = (const float*)d_in[5];
  const float* bhh_l = (const float*)d_in[6];
  const float* Wih_r = (const float*)d_in[7];
  const float* Whh_r = (const float*)d_in[8];
  const float* bih_r = (const float*)d_in[9];
  const float* bhh_r = (const float*)d_in[10];
  const float* Wenc  = (const float*)d_in[11];
  const float* benc  = (const float*)d_in[12];
  float* out = (float*)d_out;

  k_precompute<<<dim3(8, 1024, 2), NTHREADS>>>(left, right, Wih_l, Wih_r,
                                               bih_l, bhh_l, bih_r, bhh_r);
  k_step0<<<32768, 256>>>();
  for (int t = 1; t < 8; t++)
    k_step<<<dim3(8, 128, 2), NTHREADS>>>(Whh_l, Whh_r, t);
  k_enc<<<dim3(2, 128), NTHREADS>>>(rel, Wenc, benc, out);
}

// round 9
// speedup vs baseline: 1.6451x; 1.6197x over previous
#include <cuda_runtime.h>
#include <cuda_bf16.h>
#include <math.h>

// N=16384 nodes, L=8, D=256, H=256, R=64. Gate order i,f,g,o.
// Strategy: all GEMMs on mma.sync bf16 with hi/lo split (3 products, ~16-bit
// mantissa). Everything pre-split to bf16 once; cp.async double-buffered
// staging; ldmatrix fragment loads; in-register epilogues.

#define NT 256

// ------------------------- device scratch (no allocs) -----------------------
__device__ float g_X[268435456];            // [2][8][16384][1024] fp32 gate preacts
__device__ float g_c[8388608];              // [2][16384][256] cell state fp32
__device__ __nv_bfloat16 g_hs_hi[16777216]; // [2 lstm][2 buf][16384][256]
__device__ __nv_bfloat16 g_hs_lo[16777216];
__device__ __nv_bfloat16 g_xs_hi[67108864]; // [2 chain][131072][256]
__device__ __nv_bfloat16 g_xs_lo[67108864];
__device__ __nv_bfloat16 g_WhhS_hi[524288]; // [2][8 strip][128(g*32+jj)][256]
__device__ __nv_bfloat16 g_WhhS_lo[524288];
__device__ __nv_bfloat16 g_WihS_hi[524288]; // [2][1024][256]
__device__ __nv_bfloat16 g_WihS_lo[524288];
__device__ __nv_bfloat16 g_WencS_hi[147456]; // [256][576]
__device__ __nv_bfloat16 g_WencS_lo[147456];
__device__ __nv_bfloat16 g_rels_hi[1048576]; // [16384][64]
__device__ __nv_bfloat16 g_rels_lo[1048576];
__device__ float g_bsum[2048];               // [2][1024] bih+bhh

// ------------------------------- helpers ------------------------------------
__device__ __forceinline__ float fsig(float x) {
  return __fdividef(1.0f, 1.0f + __expf(-x));
}
__device__ __forceinline__ float ftanh(float x) {
  return 2.0f * __fdividef(1.0f, 1.0f + __expf(-2.0f * x)) - 1.0f;
}

__device__ __forceinline__ void mma16816(float* d, const unsigned* a, const unsigned* b) {
  asm volatile(
      "mma.sync.aligned.m16n8k16.row.col.f32.bf16.bf16.f32 "
      "{%0,%1,%2,%3}, {%4,%5,%6,%7}, {%8,%9}, {%0,%1,%2,%3};\n"
      : "+f"(d[0]), "+f"(d[1]), "+f"(d[2]), "+f"(d[3])
      : "r"(a[0]), "r"(a[1]), "r"(a[2]), "r"(a[3]), "r"(b[0]), "r"(b[1]));
}
__device__ __forceinline__ void ldsm4(unsigned* r, const __nv_bfloat16* p) {
  unsigned a = (unsigned)__cvta_generic_to_shared(p);
  asm volatile("ldmatrix.sync.aligned.m8n8.x4.shared.b16 {%0,%1,%2,%3}, [%4];\n"
               : "=r"(r[0]), "=r"(r[1]), "=r"(r[2]), "=r"(r[3]) : "r"(a));
}
__device__ __forceinline__ void ldsm2(unsigned* r, const __nv_bfloat16* p) {
  unsigned a = (unsigned)__cvta_generic_to_shared(p);
  asm volatile("ldmatrix.sync.aligned.m8n8.x2.shared.b16 {%0,%1}, [%2];\n"
               : "=r"(r[0]), "=r"(r[1]) : "r"(a));
}
__device__ __forceinline__ void cpa16(void* dst, const void* src) {
  unsigned s = (unsigned)__cvta_generic_to_shared(dst);
  asm volatile("cp.async.cg.shared.global [%0], [%1], 16;\n" :: "r"(s), "l"(src));
}
#define CP_COMMIT asm volatile("cp.async.commit_group;\n")
#define CP_WAIT0  asm volatile("cp.async.wait_group 0;\n")

// Smem chunk layout: per buffer 4 arrays of [128][56] bf16 (stride 56 bf16 =
// 112B: 16B-aligned rows, conflict-free for ldmatrix: 28*qr mod 32 all distinct)
#define STR 56
#define ARR 7168     // 128*56 elems
#define BUFSZ 28672  // 4*ARR
#define SMEM_BYTES 114688

// stage one 128x32 bf16 chunk: 512 16B segs, 2 per thread
__device__ __forceinline__ void stage_pair(__nv_bfloat16* d, const __nv_bfloat16* s,
                                           long rowBase, int ld, int koff, int tid) {
#pragma unroll
  for (int i = 0; i < 2; i++) {
    int f = tid + i * NT;
    int row = f >> 2, seg = f & 3;
    cpa16(d + row * STR + seg * 8, s + (rowBase + row) * (long)ld + koff + seg * 8);
  }
}

// GM=true: B smem row c = ni*32 + wn*8 + qr (gate-major cols)
// GM=false: c = wn*32 + ni*8 + qr (plain cols)
template <bool GM>
__device__ __forceinline__ void compute_chunk(const __nv_bfloat16* ahi, const __nv_bfloat16* alo,
                                              const __nv_bfloat16* bhi, const __nv_bfloat16* blo,
                                              float acc[4][4][4], int wm, int wn, int lane) {
  const int lr = lane & 7;
  const int arofs = ((lane >> 3) & 1) * 8;  // A: +8 rows for lanes 8-15,24-31
  const int akb = (lane >> 4) * 8;          // A: k+8 for lanes 16-31
  const int bkb = ((lane >> 3) & 1) * 8;    // B: k+8 for lanes 8-15
#pragma unroll
  for (int kk = 0; kk < 32; kk += 16) {
    unsigned ah[4][4], al[4][4], bh[4][2], bl[4][2];
#pragma unroll
    for (int mi = 0; mi < 4; mi++) {
      int r = wm * 64 + mi * 16 + lr + arofs;
      ldsm4(ah[mi], ahi + r * STR + kk + akb);
      ldsm4(al[mi], alo + r * STR + kk + akb);
    }
#pragma unroll
    for (int ni = 0; ni < 4; ni++) {
      int c = (GM ? ni * 32 + wn * 8 : wn * 32 + ni * 8) + lr;
      ldsm2(bh[ni], bhi + c * STR + kk + bkb);
      ldsm2(bl[ni], blo + c * STR + kk + bkb);
    }
#pragma unroll
    for (int mi = 0; mi < 4; mi++)
#pragma unroll
      for (int ni = 0; ni < 4; ni++) {
        mma16816(acc[mi][ni], ah[mi], bh[ni]);
        mma16816(acc[mi][ni], ah[mi], bl[ni]);
        mma16816(acc[mi][ni], al[mi], bh[ni]);
      }
  }
}

__device__ __forceinline__ void st_split2(__nv_bfloat16* ph, __nv_bfloat16* pl,
                                          float x, float y) {
  __nv_bfloat16 xh = __float2bfloat16(x), yh = __float2bfloat16(y);
  __nv_bfloat162 t; t.x = xh; t.y = yh;
  *(__nv_bfloat162*)ph = t;
  __nv_bfloat162 u;
  u.x = __float2bfloat16(x - __bfloat162float(xh));
  u.y = __float2bfloat16(y - __bfloat162float(yh));
  *(__nv_bfloat162*)pl = u;
}

// ---------------------------------------------------------------------------
// Split kernels (run every call; deterministic)
// ---------------------------------------------------------------------------
__global__ void k_split_x(const float* __restrict__ xl, const float* __restrict__ xr) {
  long i = (long)blockIdx.x * NT + threadIdx.x;  // [0, 16777216) float4 groups
  long chain = i >> 23;
  long j = i & 8388607;
  float4 v = *(const float4*)((chain ? xr : xl) + j * 4);
  long o = chain * 33554432 + j * 4;
  float x[4] = {v.x, v.y, v.z, v.w};
  __nv_bfloat162 h0, h1, l0, l1;
  __nv_bfloat16 b0 = __float2bfloat16(x[0]), b1 = __float2bfloat16(x[1]);
  __nv_bfloat16 b2 = __float2bfloat16(x[2]), b3 = __float2bfloat16(x[3]);
  h0.x = b0; h0.y = b1; h1.x = b2; h1.y = b3;
  l0.x = __float2bfloat16(x[0] - __bfloat162float(b0));
  l0.y = __float2bfloat16(x[1] - __bfloat162float(b1));
  l1.x = __float2bfloat16(x[2] - __bfloat162float(b2));
  l1.y = __float2bfloat16(x[3] - __bfloat162float(b3));
  *(__nv_bfloat162*)(g_xs_hi + o) = h0;
  *(__nv_bfloat162*)(g_xs_hi + o + 2) = h1;
  *(__nv_bfloat162*)(g_xs_lo + o) = l0;
  *(__nv_bfloat162*)(g_xs_lo + o + 2) = l1;
}

__global__ void k_split_misc(const float* __restrict__ Whh_l, const float* __restrict__ Whh_r,
                             const float* __restrict__ Wih_l, const float* __restrict__ Wih_r,
                             const float* __restrict__ Wenc, const float* __restrict__ rel,
                             const float* __restrict__ bih_l, const float* __restrict__ bhh_l,
                             const float* __restrict__ bih_r, const float* __restrict__ bhh_r) {
  long idx = (long)blockIdx.x * NT + threadIdx.x;
  if (idx < 524288) {
    // WhhS gather: dst ((z*8+strip)*128 + (g*32+jj))*256 + k
    long k = idx & 255;
    long r2 = idx >> 8;
    int row = (int)(r2 & 127);
    int zs = (int)(r2 >> 7);
    int strip = zs & 7, z = zs >> 3;
    int g = row >> 5, jj = row & 31;
    const float* W = z ? Whh_r : Whh_l;
    float v = W[(long)(g * 256 + strip * 32 + jj) * 256 + k];
    __nv_bfloat16 h = __float2bfloat16(v);
    g_WhhS_hi[idx] = h;
    g_WhhS_lo[idx] = __float2bfloat16(v - __bfloat162float(h));
  } else if (idx < 1048576) {
    long j = idx - 524288;
    int z = j >= 262144;
    float v = (z ? Wih_r : Wih_l)[j - (long)z * 262144];
    __nv_bfloat16 h = __float2bfloat16(v);
    g_WihS_hi[j] = h;
    g_WihS_lo[j] = __float2bfloat16(v - __bfloat162float(h));
  } else if (idx < 1196032) {
    long j = idx - 1048576;
    float v = Wenc[j];
    __nv_bfloat16 h = __float2bfloat16(v);
    g_WencS_hi[j] = h;
    g_WencS_lo[j] = __float2bfloat16(v - __bfloat162float(h));
  } else if (idx < 2244608) {
    long j = idx - 1196032;
    float v = rel[j];
    __nv_bfloat16 h = __float2bfloat16(v);
    g_rels_hi[j] = h;
    g_rels_lo[j] = __float2bfloat16(v - __bfloat162float(h));
  } else if (idx < 2246656) {
    long j = idx - 2244608;  // [0,2048)
    int z = (int)(j >> 10);
    int cc = (int)(j & 1023);
    g_bsum[j] = (z ? bih_r[cc] : bih_l[cc]) + (z ? bhh_r[cc] : bhh_l[cc]);
  }
}

// ---------------------------------------------------------------------------
// Kernel: Xpre = x @ Wih^T + bsum. grid (colTile=8, rowTile=1024, z=2).
// rows r = n*8 + l over [131072]. Plain column mapping.
// ---------------------------------------------------------------------------
__global__ __launch_bounds__(NT, 1) void k_precompute() {
  extern __shared__ __nv_bfloat16 sm[];
  const int tid = threadIdx.x;
  const int z = blockIdx.z, colTile = blockIdx.x;
  const long rowBase = (long)blockIdx.y * 128;
  const __nv_bfloat16* Ah = g_xs_hi + (long)z * 33554432;
  const __nv_bfloat16* Al = g_xs_lo + (long)z * 33554432;
  const long bRow = (long)z * 1024 + colTile * 128;

  const int wid = tid >> 5, lane = tid & 31;
  const int wm = wid & 1, wn = wid >> 1;
  const int qr = lane >> 2, qc = (lane & 3) << 1;

  float acc[4][4][4];
#pragma unroll
  for (int a = 0; a < 4; a++)
#pragma unroll
    for (int b = 0; b < 4; b++)
#pragma unroll
      for (int q = 0; q < 4; q++) acc[a][b][q] = 0.0f;

  {
    __nv_bfloat16* base = sm;
    stage_pair(base, Ah, rowBase, 256, 0, tid);
    stage_pair(base + ARR, Al, rowBase, 256, 0, tid);
    stage_pair(base + 2 * ARR, g_WihS_hi, bRow, 256, 0, tid);
    stage_pair(base + 3 * ARR, g_WihS_lo, bRow, 256, 0, tid);
    CP_COMMIT;
  }
  for (int kc = 0; kc < 8; kc++) {
    CP_WAIT0;
    __syncthreads();
    if (kc + 1 < 8) {
      __nv_bfloat16* base = sm + ((kc + 1) & 1) * BUFSZ;
      int k0 = (kc + 1) * 32;
      stage_pair(base, Ah, rowBase, 256, k0, tid);
      stage_pair(base + ARR, Al, rowBase, 256, k0, tid);
      stage_pair(base + 2 * ARR, g_WihS_hi, bRow, 256, k0, tid);
      stage_pair(base + 3 * ARR, g_WihS_lo, bRow, 256, k0, tid);
      CP_COMMIT;
    }
    const __nv_bfloat16* base = sm + (kc & 1) * BUFSZ;
    compute_chunk<false>(base, base + ARR, base + 2 * ARR, base + 3 * ARR, acc, wm, wn, lane);
  }

  // epilogue: add bias, write g_X[z][l][n][1024] (in-register, float2)
#pragma unroll
  for (int mi = 0; mi < 4; mi++) {
#pragma unroll
    for (int hh = 0; hh < 2; hh++) {
      long r = rowBase + wm * 64 + mi * 16 + qr + hh * 8;
      long n = r >> 3;
      int l = (int)(r & 7);
      float* dst = g_X + (((long)z * 8 + l) * 16384 + n) * 1024;
#pragma unroll
      for (int ni = 0; ni < 4; ni++) {
        int col = colTile * 128 + wn * 32 + ni * 8 + qc;
        float2 b2 = *(const float2*)(g_bsum + z * 1024 + col);
        float2 v = make_float2(acc[mi][ni][hh * 2] + b2.x, acc[mi][ni][hh * 2 + 1] + b2.y);
        *(float2*)(dst + col) = v;
      }
    }
  }
}

// ---------------------------------------------------------------------------
// Step 0 (h0=c0=0): c = sig(i)*tanh(g); h = sig(o)*tanh(c). Writes h buf 1.
// ---------------------------------------------------------------------------
__global__ void k_step0() {
  long i = (long)blockIdx.x * NT + threadIdx.x;  // [0, 2097152) float4 groups
  long z = i >> 20;
  long e4 = i & 1048575;
  long n = e4 >> 6;
  int j4 = (int)(e4 & 63) * 4;
  const float* xp = g_X + z * 134217728 + n * 1024 + j4;
  float4 gi = *(const float4*)xp;
  float4 gg = *(const float4*)(xp + 512);
  float4 go = *(const float4*)(xp + 768);
  float c0 = fsig(gi.x) * ftanh(gg.x);
  float c1 = fsig(gi.y) * ftanh(gg.y);
  float c2 = fsig(gi.z) * ftanh(gg.z);
  float c3 = fsig(gi.w) * ftanh(gg.w);
  *(float4*)(g_c + z * 4194304 + n * 256 + j4) = make_float4(c0, c1, c2, c3);
  float h0 = fsig(go.x) * ftanh(c0), h1 = fsig(go.y) * ftanh(c1);
  float h2 = fsig(go.z) * ftanh(c2), h3 = fsig(go.w) * ftanh(c3);
  long hb = (z * 2 + 1) * 4194304 + n * 256 + j4;
  st_split2(g_hs_hi + hb, g_hs_lo + hb, h0, h1);
  st_split2(g_hs_hi + hb + 2, g_hs_lo + hb + 2, h2, h3);
}

// ---------------------------------------------------------------------------
// Recurrent step t (1..7): gates = h_{t-1}@Whh^T + Xpre[t]; cell update.
// grid (strip=8, rowTile=128, z=2). Gate-major fragment map (ni=gate):
// each thread owns all 4 gates of its (n,j) -> register epilogue.
// ---------------------------------------------------------------------------
__global__ __launch_bounds__(NT, 1) void k_step(int t) {
  extern __shared__ __nv_bfloat16 sm[];
  const int tid = threadIdx.x;
  const int z = blockIdx.z, strip = blockIdx.x;
  const long rowBase = (long)blockIdx.y * 128;
  const __nv_bfloat16* Ah = g_hs_hi + ((long)z * 2 + (t & 1)) * 4194304;
  const __nv_bfloat16* Al = g_hs_lo + ((long)z * 2 + (t & 1)) * 4194304;
  __nv_bfloat16* hnh = g_hs_hi + ((long)z * 2 + ((t + 1) & 1)) * 4194304;
  __nv_bfloat16* hnl = g_hs_lo + ((long)z * 2 + ((t + 1) & 1)) * 4194304;
  float* cst = g_c + (long)z * 4194304;
  const float* xpre = g_X + ((long)z * 8 + t) * 16777216L;
  const long bRow = (long)(z * 8 + strip) * 128;

  const int wid = tid >> 5, lane = tid & 31;
  const int wm = wid & 1, wn = wid >> 1;
  const int qr = lane >> 2, qc = (lane & 3) << 1;

  float acc[4][4][4];
#pragma unroll
  for (int a = 0; a < 4; a++)
#pragma unroll
    for (int b = 0; b < 4; b++)
#pragma unroll
      for (int q = 0; q < 4; q++) acc[a][b][q] = 0.0f;

  {
    __nv_bfloat16* base = sm;
    stage_pair(base, Ah, rowBase, 256, 0, tid);
    stage_pair(base + ARR, Al, rowBase, 256, 0, tid);
    stage_pair(base + 2 * ARR, g_WhhS_hi, bRow, 256, 0, tid);
    stage_pair(base + 3 * ARR, g_WhhS_lo, bRow, 256, 0, tid);
    CP_COMMIT;
  }
  for (int kc = 0; kc < 8; kc++) {
    CP_WAIT0;
    __syncthreads();
    if (kc + 1 < 8) {
      __nv_bfloat16* base = sm + ((kc + 1) & 1) * BUFSZ;
      int k0 = (kc + 1) * 32;
      stage_pair(base, Ah, rowBase, 256, k0, tid);
      stage_pair(base + ARR, Al, rowBase, 256, k0, tid);
      stage_pair(base + 2 * ARR, g_WhhS_hi, bRow, 256, k0, tid);
      stage_pair(base + 3 * ARR, g_WhhS_lo, bRow, 256, k0, tid);
      CP_COMMIT;
    }
    const __nv_bfloat16* base = sm + (kc & 1) * BUFSZ;
    compute_chunk<true>(base, base + ARR, base + 2 * ARR, base + 3 * ARR, acc, wm, wn, lane);
  }

  // register epilogue: ni=0..3 -> gates i,f,g,o of j = strip*32 + wn*8 + qc
  const int jloc = strip * 32 + wn * 8 + qc;
#pragma unroll
  for (int mi = 0; mi < 4; mi++) {
#pragma unroll
    for (int hh = 0; hh < 2; hh++) {
      const long n = rowBase + wm * 64 + mi * 16 + qr + hh * 8;
      const float* xp = xpre + n * 1024 + jloc;
      float2 xi = *(const float2*)xp;
      float2 xf = *(const float2*)(xp + 256);
      float2 xg = *(const float2*)(xp + 512);
      float2 xo = *(const float2*)(xp + 768);
      float2 cp2 = *(const float2*)(cst + n * 256 + jloc);
      const int b = hh * 2;
      float gi0 = acc[mi][0][b] + xi.x, gi1 = acc[mi][0][b + 1] + xi.y;
      float gf0 = acc[mi][1][b] + xf.x, gf1 = acc[mi][1][b + 1] + xf.y;
      float gg0 = acc[mi][2][b] + xg.x, gg1 = acc[mi][2][b + 1] + xg.y;
      float go0 = acc[mi][3][b] + xo.x, go1 = acc[mi][3][b + 1] + xo.y;
      float c0 = fsig(gf0) * cp2.x + fsig(gi0) * ftanh(gg0);
      float c1 = fsig(gf1) * cp2.y + fsig(gi1) * ftanh(gg1);
      *(float2*)(cst + n * 256 + jloc) = make_float2(c0, c1);
      float h0 = fsig(go0) * ftanh(c0);
      float h1 = fsig(go1) * ftanh(c1);
      st_split2(hnh + n * 256 + jloc, hnl + n * 256 + jloc, h0, h1);
    }
  }
}

// ---------------------------------------------------------------------------
// Encoder: out = tanh([hl, hr, rel] @ Wenc^T + benc). grid (colTile=2, rowTile=128)
// K = 576 = 18 chunks; A source switches hl -> hr -> rel. h final in buf 0.
// ---------------------------------------------------------------------------
__device__ __forceinline__ void enc_stageA(__nv_bfloat16* dh, __nv_bfloat16* dl,
                                           long rowBase, int kc, int tid) {
  const __nv_bfloat16 *sh, *sl;
  int ld, koff;
  if (kc < 8)       { sh = g_hs_hi;               sl = g_hs_lo;               ld = 256; koff = kc * 32; }
  else if (kc < 16) { sh = g_hs_hi + 2L * 4194304; sl = g_hs_lo + 2L * 4194304; ld = 256; koff = (kc - 8) * 32; }
  else              { sh = g_rels_hi;             sl = g_rels_lo;             ld = 64;  koff = (kc - 16) * 32; }
  stage_pair(dh, sh, rowBase, ld, koff, tid);
  stage_pair(dl, sl, rowBase, ld, koff, tid);
}

__global__ __launch_bounds__(NT, 1) void k_enc(const float* __restrict__ benc,
                                               float* __restrict__ out) {
  extern __shared__ __nv_bfloat16 sm[];
  const int tid = threadIdx.x;
  const int colTile = blockIdx.x;
  const long rowBase = (long)blockIdx.y * 128;
  const long bRow = (long)colTile * 128;

  const int wid = tid >> 5, lane = tid & 31;
  const int wm = wid & 1, wn = wid >> 1;
  const int qr = lane >> 2, qc = (lane & 3) << 1;

  float acc[4][4][4];
#pragma unroll
  for (int a = 0; a < 4; a++)
#pragma unroll
    for (int b = 0; b < 4; b++)
#pragma unroll
      for (int q = 0; q < 4; q++) acc[a][b][q] = 0.0f;

  {
    __nv_bfloat16* base = sm;
    enc_stageA(base, base + ARR, rowBase, 0, tid);
    stage_pair(base + 2 * ARR, g_WencS_hi, bRow, 576, 0, tid);
    stage_pair(base + 3 * ARR, g_WencS_lo, bRow, 576, 0, tid);
    CP_COMMIT;
  }
  for (int kc = 0; kc < 18; kc++) {
    CP_WAIT0;
    __syncthreads();
    if (kc + 1 < 18) {
      __nv_bfloat16* base = sm + ((kc + 1) & 1) * BUFSZ;
      enc_stageA(base, base + ARR, rowBase, kc + 1, tid);
      stage_pair(base + 2 * ARR, g_WencS_hi, bRow, 576, (kc + 1) * 32, tid);
      stage_pair(base + 3 * ARR, g_WencS_lo, bRow, 576, (kc + 1) * 32, tid);
      CP_COMMIT;
    }
    const __nv_bfloat16* base = sm + (kc & 1) * BUFSZ;
    compute_chunk<false>(base, base + ARR, base + 2 * ARR, base + 3 * ARR, acc, wm, wn, lane);
  }

#pragma unroll
  for (int mi = 0; mi < 4; mi++) {
#pragma unroll
    for (int hh = 0; hh < 2; hh++) {
      long n = rowBase + wm * 64 + mi * 16 + qr + hh * 8;
#pragma unroll
      for (int ni = 0; ni < 4; ni++) {
        int col = colTile * 128 + wn * 32 + ni * 8 + qc;
        float2 b2 = *(const float2*)(benc + col);
        float v0 = ftanh(acc[mi][ni][hh * 2] + b2.x);
        float v1 = ftanh(acc[mi][ni][hh * 2 + 1] + b2.y);
        *(float2*)(out + n * 256 + col) = make_float2(v0, v1);
      }
    }
  }
}

// ---------------------------------------------------------------------------
extern "C" void kernel_launch(void* const* d_in, const int* in_sizes, int n_in,
                              void* d_out, int out_size) {
  (void)in_sizes; (void)n_in; (void)out_size;
  const float* left  = (const float*)d_in[0];
  const float* right = (const float*)d_in[1];
  const float* rel   = (const float*)d_in[2];
  const float* Wih_l = (const float*)d_in[3];
  const float* Whh_l = (const float*)d_in[4];
  const float* bih_l = (const float*)d_in[5];
  const float* bhh_l = (const float*)d_in[6];
  const float* Wih_r = (const float*)d_in[7];
  const float* Whh_r = (const float*)d_in[8];
  const float* bih_r = (const float*)d_in[9];
  const float* bhh_r = (const float*)d_in[10];
  const float* Wenc  = (const float*)d_in[11];
  const float* benc  = (const float*)d_in[12];
  float* out = (float*)d_out;

  cudaFuncSetAttribute(k_precompute, cudaFuncAttributeMaxDynamicSharedMemorySize, SMEM_BYTES);
  cudaFuncSetAttribute(k_step, cudaFuncAttributeMaxDynamicSharedMemorySize, SMEM_BYTES);
  cudaFuncSetAttribute(k_enc, cudaFuncAttributeMaxDynamicSharedMemorySize, SMEM_BYTES);

  k_split_x<<<65536, NT>>>(left, right);
  k_split_misc<<<8776, NT>>>(Whh_l, Whh_r, Wih_l, Wih_r, Wenc, rel,
                             bih_l, bhh_l, bih_r, bhh_r);
  k_precompute<<<dim3(8, 1024, 2), NT, SMEM_BYTES>>>();
  k_step0<<<8192, NT>>>();
  for (int t = 1; t < 8; t++)
    k_step<<<dim3(8, 128, 2), NT, SMEM_BYTES>>>(t);
  k_enc<<<dim3(2, 128), NT, SMEM_BYTES>>>(benc, out);
}

// round 10
// speedup vs baseline: 1.7721x; 1.0772x over previous
#include <cuda_runtime.h>
#include <cuda_bf16.h>
#include <math.h>

// N=16384 nodes, L=8, D=256, H=256, R=64. Gate order i,f,g,o.
// Fused recurrence: gates_t = [h_{t-1} | x_t] @ [Whh | Wih]^T + b  (K=512 GEMM
// per step, no Xpre materialization). All GEMMs: mma.sync bf16 hi/lo split
// (3 products ~= 16-bit mantissa), cp.async double-buffered, ldmatrix loads,
// in-register epilogues.

#define NT 256

// ------------------------- device scratch (no allocs) -----------------------
__device__ float g_c[8388608];               // [2][16384][256] cell state fp32
__device__ __nv_bfloat16 g_hs_hi[16777216];  // [2 lstm][2 buf][16384][256]
__device__ __nv_bfloat16 g_hs_lo[16777216];
__device__ __nv_bfloat16 g_xs_hi[67108864];  // [2 chain][16384*8 (n*8+l)][256]
__device__ __nv_bfloat16 g_xs_lo[67108864];
__device__ __nv_bfloat16 g_Wcomb_hi[1048576]; // [2][8 strip][128(g*32+jj)][512(Whh|Wih)]
__device__ __nv_bfloat16 g_Wcomb_lo[1048576];
__device__ __nv_bfloat16 g_WencS_hi[147456];  // [256][576]
__device__ __nv_bfloat16 g_WencS_lo[147456];
__device__ __nv_bfloat16 g_rels_hi[1048576];  // [16384][64]
__device__ __nv_bfloat16 g_rels_lo[1048576];
__device__ float g_bsum[2048];                // [2][1024] bih+bhh

// ------------------------------- helpers ------------------------------------
__device__ __forceinline__ float fsig(float x) {
  return __fdividef(1.0f, 1.0f + __expf(-x));
}
__device__ __forceinline__ float ftanh(float x) {
  return 2.0f * __fdividef(1.0f, 1.0f + __expf(-2.0f * x)) - 1.0f;
}

__device__ __forceinline__ void mma16816(float* d, const unsigned* a, const unsigned* b) {
  asm volatile(
      "mma.sync.aligned.m16n8k16.row.col.f32.bf16.bf16.f32 "
      "{%0,%1,%2,%3}, {%4,%5,%6,%7}, {%8,%9}, {%0,%1,%2,%3};\n"
      : "+f"(d[0]), "+f"(d[1]), "+f"(d[2]), "+f"(d[3])
      : "r"(a[0]), "r"(a[1]), "r"(a[2]), "r"(a[3]), "r"(b[0]), "r"(b[1]));
}
__device__ __forceinline__ void ldsm4(unsigned* r, const __nv_bfloat16* p) {
  unsigned a = (unsigned)__cvta_generic_to_shared(p);
  asm volatile("ldmatrix.sync.aligned.m8n8.x4.shared.b16 {%0,%1,%2,%3}, [%4];\n"
               : "=r"(r[0]), "=r"(r[1]), "=r"(r[2]), "=r"(r[3]) : "r"(a));
}
__device__ __forceinline__ void ldsm2(unsigned* r, const __nv_bfloat16* p) {
  unsigned a = (unsigned)__cvta_generic_to_shared(p);
  asm volatile("ldmatrix.sync.aligned.m8n8.x2.shared.b16 {%0,%1}, [%2];\n"
               : "=r"(r[0]), "=r"(r[1]) : "r"(a));
}
__device__ __forceinline__ void cpa16(void* dst, const void* src) {
  unsigned s = (unsigned)__cvta_generic_to_shared(dst);
  asm volatile("cp.async.cg.shared.global [%0], [%1], 16;\n" :: "r"(s), "l"(src));
}
#define CP_COMMIT asm volatile("cp.async.commit_group;\n")
#define CP_WAIT0  asm volatile("cp.async.wait_group 0;\n")

// Smem chunk layout: per buffer 4 arrays of [128][56] bf16 (stride 56 = 112B,
// 16B-aligned rows, conflict-free ldmatrix)
#define STR 56
#define ARR 7168     // 128*56 elems
#define BUFSZ 28672  // 4*ARR
#define SMEM_BYTES 114688

// stage one 128x32 bf16 chunk: 512 16B segs, 2 per thread
__device__ __forceinline__ void stage_pair(__nv_bfloat16* d, const __nv_bfloat16* s,
                                           long rowBase, int ld, int koff, int tid) {
#pragma unroll
  for (int i = 0; i < 2; i++) {
    int f = tid + i * NT;
    int row = f >> 2, seg = f & 3;
    cpa16(d + row * STR + seg * 8, s + (rowBase + row) * (long)ld + koff + seg * 8);
  }
}

// GM=true: B smem row c = ni*32 + wn*8 + qr (gate-major cols)
// GM=false: c = wn*32 + ni*8 + qr (plain cols)
template <bool GM>
__device__ __forceinline__ void compute_chunk(const __nv_bfloat16* ahi, const __nv_bfloat16* alo,
                                              const __nv_bfloat16* bhi, const __nv_bfloat16* blo,
                                              float acc[4][4][4], int wm, int wn, int lane) {
  const int lr = lane & 7;
  const int arofs = ((lane >> 3) & 1) * 8;
  const int akb = (lane >> 4) * 8;
  const int bkb = ((lane >> 3) & 1) * 8;
#pragma unroll
  for (int kk = 0; kk < 32; kk += 16) {
    unsigned ah[4][4], al[4][4], bh[4][2], bl[4][2];
#pragma unroll
    for (int mi = 0; mi < 4; mi++) {
      int r = wm * 64 + mi * 16 + lr + arofs;
      ldsm4(ah[mi], ahi + r * STR + kk + akb);
      ldsm4(al[mi], alo + r * STR + kk + akb);
    }
#pragma unroll
    for (int ni = 0; ni < 4; ni++) {
      int c = (GM ? ni * 32 + wn * 8 : wn * 32 + ni * 8) + lr;
      ldsm2(bh[ni], bhi + c * STR + kk + bkb);
      ldsm2(bl[ni], blo + c * STR + kk + bkb);
    }
#pragma unroll
    for (int mi = 0; mi < 4; mi++)
#pragma unroll
      for (int ni = 0; ni < 4; ni++) {
        mma16816(acc[mi][ni], ah[mi], bh[ni]);
        mma16816(acc[mi][ni], ah[mi], bl[ni]);
        mma16816(acc[mi][ni], al[mi], bh[ni]);
      }
  }
}

__device__ __forceinline__ void st_split2(__nv_bfloat16* ph, __nv_bfloat16* pl,
                                          float x, float y) {
  __nv_bfloat16 xh = __float2bfloat16(x), yh = __float2bfloat16(y);
  __nv_bfloat162 t; t.x = xh; t.y = yh;
  *(__nv_bfloat162*)ph = t;
  __nv_bfloat162 u;
  u.x = __float2bfloat16(x - __bfloat162float(xh));
  u.y = __float2bfloat16(y - __bfloat162float(yh));
  *(__nv_bfloat162*)pl = u;
}

// ---------------------------------------------------------------------------
// Split kernels (run every call; deterministic)
// ---------------------------------------------------------------------------
__global__ void k_split_x(const float* __restrict__ xl, const float* __restrict__ xr) {
  long i = (long)blockIdx.x * NT + threadIdx.x;  // [0, 16777216) float4 groups
  long chain = i >> 23;
  long j = i & 8388607;
  float4 v = *(const float4*)((chain ? xr : xl) + j * 4);
  long o = chain * 33554432 + j * 4;
  float x[4] = {v.x, v.y, v.z, v.w};
  __nv_bfloat162 h0, h1, l0, l1;
  __nv_bfloat16 b0 = __float2bfloat16(x[0]), b1 = __float2bfloat16(x[1]);
  __nv_bfloat16 b2 = __float2bfloat16(x[2]), b3 = __float2bfloat16(x[3]);
  h0.x = b0; h0.y = b1; h1.x = b2; h1.y = b3;
  l0.x = __float2bfloat16(x[0] - __bfloat162float(b0));
  l0.y = __float2bfloat16(x[1] - __bfloat162float(b1));
  l1.x = __float2bfloat16(x[2] - __bfloat162float(b2));
  l1.y = __float2bfloat16(x[3] - __bfloat162float(b3));
  *(__nv_bfloat162*)(g_xs_hi + o) = h0;
  *(__nv_bfloat162*)(g_xs_hi + o + 2) = h1;
  *(__nv_bfloat162*)(g_xs_lo + o) = l0;
  *(__nv_bfloat162*)(g_xs_lo + o + 2) = l1;
}

__global__ void k_split_misc(const float* __restrict__ Whh_l, const float* __restrict__ Whh_r,
                             const float* __restrict__ Wih_l, const float* __restrict__ Wih_r,
                             const float* __restrict__ Wenc, const float* __restrict__ rel,
                             const float* __restrict__ bih_l, const float* __restrict__ bhh_l,
                             const float* __restrict__ bih_r, const float* __restrict__ bhh_r) {
  long idx = (long)blockIdx.x * NT + threadIdx.x;
  if (idx < 1048576) {
    // Wcomb gather: dst (((z*8+strip)*128 + (g*32+jj))*512 + k
    // k<256 -> Whh[g*256+strip*32+jj][k]; k>=256 -> Wih[...][k-256]
    int k = (int)(idx & 511);
    long r2 = idx >> 9;
    int row = (int)(r2 & 127);
    int zs = (int)(r2 >> 7);
    int strip = zs & 7, z = zs >> 3;
    int g = row >> 5, jj = row & 31;
    long wrow = (long)(g * 256 + strip * 32 + jj) * 256;
    float v;
    if (k < 256) v = (z ? Whh_r : Whh_l)[wrow + k];
    else         v = (z ? Wih_r : Wih_l)[wrow + k - 256];
    __nv_bfloat16 h = __float2bfloat16(v);
    g_Wcomb_hi[idx] = h;
    g_Wcomb_lo[idx] = __float2bfloat16(v - __bfloat162float(h));
  } else if (idx < 1196032) {
    long j = idx - 1048576;
    float v = Wenc[j];
    __nv_bfloat16 h = __float2bfloat16(v);
    g_WencS_hi[j] = h;
    g_WencS_lo[j] = __float2bfloat16(v - __bfloat162float(h));
  } else if (idx < 2244608) {
    long j = idx - 1196032;
    float v = rel[j];
    __nv_bfloat16 h = __float2bfloat16(v);
    g_rels_hi[j] = h;
    g_rels_lo[j] = __float2bfloat16(v - __bfloat162float(h));
  } else if (idx < 2246656) {
    long j = idx - 2244608;  // [0,2048)
    int z = (int)(j >> 10);
    int cc = (int)(j & 1023);
    g_bsum[j] = (z ? bih_r[cc] : bih_l[cc]) + (z ? bhh_r[cc] : bhh_l[cc]);
  }
}

// Zero the h input buffers (buf 0 of each lstm) for t=0.
__global__ void k_zero_h() {
  long i = (long)blockIdx.x * NT + threadIdx.x;  // [0, 1048576) uint4 groups
  long z = i >> 19;
  long o = z * 8388608 + (i & 524287) * 8;  // elems
  uint4 zz = make_uint4(0, 0, 0, 0);
  *(uint4*)(g_hs_hi + o) = zz;
  *(uint4*)(g_hs_lo + o) = zz;
}

// ---------------------------------------------------------------------------
// Fused recurrent step t (0..7): gates = [h_{t-1} | x_t] @ Wcomb^T + bsum.
// grid (strip=8, rowTile=128, z=2). K=512 = 16 chunks (8 from h, 8 from x).
// Gate-major fragment map (ni=gate): register cell-update epilogue.
// h double-buffered: read buf[t&1], write buf[(t+1)&1]; c in place (t=0: c=0).
// ---------------------------------------------------------------------------
__device__ __forceinline__ void step_stageA(__nv_bfloat16* dh, __nv_bfloat16* dl,
                                            long rowBase, int kc, int t, int z, int tid) {
  if (kc < 8) {
    long off = ((long)z * 2 + (t & 1)) * 4194304;
    stage_pair(dh, g_hs_hi + off, rowBase, 256, kc * 32, tid);
    stage_pair(dl, g_hs_lo + off, rowBase, 256, kc * 32, tid);
  } else {
    long off = (long)z * 33554432 + t * 256;  // row n -> (n*8+t)*256
    stage_pair(dh, g_xs_hi + off, rowBase, 2048, (kc - 8) * 32, tid);
    stage_pair(dl, g_xs_lo + off, rowBase, 2048, (kc - 8) * 32, tid);
  }
}

__global__ __launch_bounds__(NT, 1) void k_step(int t) {
  extern __shared__ __nv_bfloat16 sm[];
  const int tid = threadIdx.x;
  const int z = blockIdx.z, strip = blockIdx.x;
  const long rowBase = (long)blockIdx.y * 128;
  __nv_bfloat16* hnh = g_hs_hi + ((long)z * 2 + ((t + 1) & 1)) * 4194304;
  __nv_bfloat16* hnl = g_hs_lo + ((long)z * 2 + ((t + 1) & 1)) * 4194304;
  float* cst = g_c + (long)z * 4194304;
  const long bRow = (long)(z * 8 + strip) * 128;

  const int wid = tid >> 5, lane = tid & 31;
  const int wm = wid & 1, wn = wid >> 1;
  const int qr = lane >> 2, qc = (lane & 3) << 1;

  float acc[4][4][4];
#pragma unroll
  for (int a = 0; a < 4; a++)
#pragma unroll
    for (int b = 0; b < 4; b++)
#pragma unroll
      for (int q = 0; q < 4; q++) acc[a][b][q] = 0.0f;

  {
    __nv_bfloat16* base = sm;
    step_stageA(base, base + ARR, rowBase, 0, t, z, tid);
    stage_pair(base + 2 * ARR, g_Wcomb_hi, bRow, 512, 0, tid);
    stage_pair(base + 3 * ARR, g_Wcomb_lo, bRow, 512, 0, tid);
    CP_COMMIT;
  }
  for (int kc = 0; kc < 16; kc++) {
    CP_WAIT0;
    __syncthreads();
    if (kc + 1 < 16) {
      __nv_bfloat16* base = sm + ((kc + 1) & 1) * BUFSZ;
      step_stageA(base, base + ARR, rowBase, kc + 1, t, z, tid);
      stage_pair(base + 2 * ARR, g_Wcomb_hi, bRow, 512, (kc + 1) * 32, tid);
      stage_pair(base + 3 * ARR, g_Wcomb_lo, bRow, 512, (kc + 1) * 32, tid);
      CP_COMMIT;
    }
    const __nv_bfloat16* base = sm + (kc & 1) * BUFSZ;
    compute_chunk<true>(base, base + ARR, base + 2 * ARR, base + 3 * ARR, acc, wm, wn, lane);
  }

  // register epilogue: ni -> gate (i,f,g,o) of j = strip*32 + wn*8 + qc
  const int jloc = strip * 32 + wn * 8 + qc;
  const float* bs = g_bsum + z * 1024;
  const float2 bi2 = *(const float2*)(bs + jloc);
  const float2 bf2 = *(const float2*)(bs + 256 + jloc);
  const float2 bg2 = *(const float2*)(bs + 512 + jloc);
  const float2 bo2 = *(const float2*)(bs + 768 + jloc);
#pragma unroll
  for (int mi = 0; mi < 4; mi++) {
#pragma unroll
    for (int hh = 0; hh < 2; hh++) {
      const long n = rowBase + wm * 64 + mi * 16 + qr + hh * 8;
      float2 cp2 = make_float2(0.0f, 0.0f);
      if (t) cp2 = *(const float2*)(cst + n * 256 + jloc);
      const int b = hh * 2;
      float gi0 = acc[mi][0][b] + bi2.x, gi1 = acc[mi][0][b + 1] + bi2.y;
      float gf0 = acc[mi][1][b] + bf2.x, gf1 = acc[mi][1][b + 1] + bf2.y;
      float gg0 = acc[mi][2][b] + bg2.x, gg1 = acc[mi][2][b + 1] + bg2.y;
      float go0 = acc[mi][3][b] + bo2.x, go1 = acc[mi][3][b + 1] + bo2.y;
      float c0 = fsig(gf0) * cp2.x + fsig(gi0) * ftanh(gg0);
      float c1 = fsig(gf1) * cp2.y + fsig(gi1) * ftanh(gg1);
      *(float2*)(cst + n * 256 + jloc) = make_float2(c0, c1);
      float h0 = fsig(go0) * ftanh(c0);
      float h1 = fsig(go1) * ftanh(c1);
      st_split2(hnh + n * 256 + jloc, hnl + n * 256 + jloc, h0, h1);
    }
  }
}

// ---------------------------------------------------------------------------
// Encoder: out = tanh([hl, hr, rel] @ Wenc^T + benc). grid (colTile=2, rowTile=128)
// K = 576 = 18 chunks; A source hl -> hr -> rel. Final h in buf 0.
// ---------------------------------------------------------------------------
__device__ __forceinline__ void enc_stageA(__nv_bfloat16* dh, __nv_bfloat16* dl,
                                           long rowBase, int kc, int tid) {
  const __nv_bfloat16 *sh, *sl;
  int ld, koff;
  if (kc < 8)       { sh = g_hs_hi;                sl = g_hs_lo;                ld = 256; koff = kc * 32; }
  else if (kc < 16) { sh = g_hs_hi + 2L * 4194304; sl = g_hs_lo + 2L * 4194304; ld = 256; koff = (kc - 8) * 32; }
  else              { sh = g_rels_hi;              sl = g_rels_lo;              ld = 64;  koff = (kc - 16) * 32; }
  stage_pair(dh, sh, rowBase, ld, koff, tid);
  stage_pair(dl, sl, rowBase, ld, koff, tid);
}

__global__ __launch_bounds__(NT, 1) void k_enc(const float* __restrict__ benc,
                                               float* __restrict__ out) {
  extern __shared__ __nv_bfloat16 sm[];
  const int tid = threadIdx.x;
  const int colTile = blockIdx.x;
  const long rowBase = (long)blockIdx.y * 128;
  const long bRow = (long)colTile * 128;

  const int wid = tid >> 5, lane = tid & 31;
  const int wm = wid & 1, wn = wid >> 1;
  const int qr = lane >> 2, qc = (lane & 3) << 1;

  float acc[4][4][4];
#pragma unroll
  for (int a = 0; a < 4; a++)
#pragma unroll
    for (int b = 0; b < 4; b++)
#pragma unroll
      for (int q = 0; q < 4; q++) acc[a][b][q] = 0.0f;

  {
    __nv_bfloat16* base = sm;
    enc_stageA(base, base + ARR, rowBase, 0, tid);
    stage_pair(base + 2 * ARR, g_WencS_hi, bRow, 576, 0, tid);
    stage_pair(base + 3 * ARR, g_WencS_lo, bRow, 576, 0, tid);
    CP_COMMIT;
  }
  for (int kc = 0; kc < 18; kc++) {
    CP_WAIT0;
    __syncthreads();
    if (kc + 1 < 18) {
      __nv_bfloat16* base = sm + ((kc + 1) & 1) * BUFSZ;
      enc_stageA(base, base + ARR, rowBase, kc + 1, tid);
      stage_pair(base + 2 * ARR, g_WencS_hi, bRow, 576, (kc + 1) * 32, tid);
      stage_pair(base + 3 * ARR, g_WencS_lo, bRow, 576, (kc + 1) * 32, tid);
      CP_COMMIT;
    }
    const __nv_bfloat16* base = sm + (kc & 1) * BUFSZ;
    compute_chunk<false>(base, base + ARR, base + 2 * ARR, base + 3 * ARR, acc, wm, wn, lane);
  }

#pragma unroll
  for (int mi = 0; mi < 4; mi++) {
#pragma unroll
    for (int hh = 0; hh < 2; hh++) {
      long n = rowBase + wm * 64 + mi * 16 + qr + hh * 8;
#pragma unroll
      for (int ni = 0; ni < 4; ni++) {
        int col = colTile * 128 + wn * 32 + ni * 8 + qc;
        float2 b2 = *(const float2*)(benc + col);
        float v0 = ftanh(acc[mi][ni][hh * 2] + b2.x);
        float v1 = ftanh(acc[mi][ni][hh * 2 + 1] + b2.y);
        *(float2*)(out + n * 256 + col) = make_float2(v0, v1);
      }
    }
  }
}

// ---------------------------------------------------------------------------
extern "C" void kernel_launch(void* const* d_in, const int* in_sizes, int n_in,
                              void* d_out, int out_size) {
  (void)in_sizes; (void)n_in; (void)out_size;
  const float* left  = (const float*)d_in[0];
  const float* right = (const float*)d_in[1];
  const float* rel   = (const float*)d_in[2];
  const float* Wih_l = (const float*)d_in[3];
  const float* Whh_l = (const float*)d_in[4];
  const float* bih_l = (const float*)d_in[5];
  const float* bhh_l = (const float*)d_in[6];
  const float* Wih_r = (const float*)d_in[7];
  const float* Whh_r = (const float*)d_in[8];
  const float* bih_r = (const float*)d_in[9];
  const float* bhh_r = (const float*)d_in[10];
  const float* Wenc  = (const float*)d_in[11];
  const float* benc  = (const float*)d_in[12];
  float* out = (float*)d_out;

  cudaFuncSetAttribute(k_step, cudaFuncAttributeMaxDynamicSharedMemorySize, SMEM_BYTES);
  cudaFuncSetAttribute(k_enc, cudaFuncAttributeMaxDynamicSharedMemorySize, SMEM_BYTES);

  k_split_x<<<65536, NT>>>(left, right);
  k_split_misc<<<8776, NT>>>(Whh_l, Whh_r, Wih_l, Wih_r, Wenc, rel,
                             bih_l, bhh_l, bih_r, bhh_r);
  k_zero_h<<<4096, NT>>>();
  for (int t = 0; t < 8; t++)
    k_step<<<dim3(8, 128, 2), NT, SMEM_BYTES>>>(t);
  k_enc<<<dim3(2, 128), NT, SMEM_BYTES>>>(benc, out);
}

// round 12
// speedup vs baseline: 2.5613x; 1.4453x over previous
#include <cuda_runtime.h>
#include <cuda_bf16.h>
#include <math.h>

// N=16384 nodes, L=8, D=256, H=256, R=64. Gate order i,f,g,o.
// Fused recurrence: gates_t = [h_{t-1} | x_t] @ [Whh | Wih]^T + b (K=512 GEMM
// per step). mma.sync bf16 hi/lo split (3 products), XOR-swizzled smem
// (64KB/CTA -> 2 CTAs/SM), product-outer MMA ordering (no RAW chains),
// cp.async double-buffered, ldmatrix loads, in-register epilogues.

#define NT 256

// ------------------------- device scratch (no allocs) -----------------------
__device__ float g_c[8388608];               // [2][16384][256] cell state fp32
__device__ __nv_bfloat16 g_hs_hi[16777216];  // [2 lstm][2 buf][16384][256]
__device__ __nv_bfloat16 g_hs_lo[16777216];
__device__ __nv_bfloat16 g_xs_hi[67108864];  // [2 chain][16384*8 (n*8+l)][256]
__device__ __nv_bfloat16 g_xs_lo[67108864];
__device__ __nv_bfloat16 g_Wcomb_hi[1048576]; // [2][8 strip][128(g*32+jj)][512(Whh|Wih)]
__device__ __nv_bfloat16 g_Wcomb_lo[1048576];
__device__ __nv_bfloat16 g_WencS_hi[147456];  // [256][576]
__device__ __nv_bfloat16 g_WencS_lo[147456];
__device__ __nv_bfloat16 g_rels_hi[1048576];  // [16384][64]
__device__ __nv_bfloat16 g_rels_lo[1048576];
__device__ float g_bsum[2048];                // [2][1024] bih+bhh

// ------------------------------- helpers ------------------------------------
__device__ __forceinline__ float fsig(float x) {
  return __fdividef(1.0f, 1.0f + __expf(-x));
}
__device__ __forceinline__ float ftanh(float x) {
  return 2.0f * __fdividef(1.0f, 1.0f + __expf(-2.0f * x)) - 1.0f;
}

__device__ __forceinline__ void mma16816(float* d, const unsigned* a, const unsigned* b) {
  asm volatile(
      "mma.sync.aligned.m16n8k16.row.col.f32.bf16.bf16.f32 "
      "{%0,%1,%2,%3}, {%4,%5,%6,%7}, {%8,%9}, {%0,%1,%2,%3};\n"
      : "+f"(d[0]), "+f"(d[1]), "+f"(d[2]), "+f"(d[3])
      : "r"(a[0]), "r"(a[1]), "r"(a[2]), "r"(a[3]), "r"(b[0]), "r"(b[1]));
}
__device__ __forceinline__ void ldsm4(unsigned* r, const __nv_bfloat16* p) {
  unsigned a = (unsigned)__cvta_generic_to_shared(p);
  asm volatile("ldmatrix.sync.aligned.m8n8.x4.shared.b16 {%0,%1,%2,%3}, [%4];\n"
               : "=r"(r[0]), "=r"(r[1]), "=r"(r[2]), "=r"(r[3]) : "r"(a));
}
__device__ __forceinline__ void ldsm2(unsigned* r, const __nv_bfloat16* p) {
  unsigned a = (unsigned)__cvta_generic_to_shared(p);
  asm volatile("ldmatrix.sync.aligned.m8n8.x2.shared.b16 {%0,%1}, [%2];\n"
               : "=r"(r[0]), "=r"(r[1]) : "r"(a));
}
__device__ __forceinline__ void cpa16(void* dst, const void* src) {
  unsigned s = (unsigned)__cvta_generic_to_shared(dst);
  asm volatile("cp.async.cg.shared.global [%0], [%1], 16;\n" :: "r"(s), "l"(src));
}
#define CP_COMMIT asm volatile("cp.async.commit_group;\n")
#define CP_WAIT0  asm volatile("cp.async.wait_group 0;\n")

// XOR-swizzled smem layout: array [128 rows][32 bf16] (64B rows, no pad).
// Element offset for (row r, 16B-seg s in 0..3): r*32 + ((s ^ ((r>>1)&3))<<3).
// Any 8 consecutive rows at fixed s hit 8 distinct 16B bank groups ->
// conflict-free ldmatrix AND conflict-free cp.async staging.
#define SWZ(r, s) ((r) * 32 + ((((s) ^ (((r) >> 1) & 3))) << 3))
#define ARR 4096     // 128*32 elems per array
#define BUFSZ 16384  // 4*ARR elems per buffer
#define SMEM_BYTES 65536

// stage one 128x32 bf16 chunk: 512 16B segs, 2 per thread
__device__ __forceinline__ void stage_pair(__nv_bfloat16* d, const __nv_bfloat16* s,
                                           long rowBase, int ld, int koff, int tid) {
#pragma unroll
  for (int i = 0; i < 2; i++) {
    int f = tid + i * NT;
    int row = f >> 2, seg = f & 3;
    cpa16(d + SWZ(row, seg), s + (rowBase + row) * (long)ld + koff + seg * 8);
  }
}

// GM=true: B smem row c = ni*32 + wn*8 + qr (gate-major cols)
// GM=false: c = wn*32 + ni*8 + qr (plain cols)
// Product-outer MMA order: same-acc MMAs separated by 16 independent issues.
template <bool GM>
__device__ __forceinline__ void compute_chunk(const __nv_bfloat16* ahi, const __nv_bfloat16* alo,
                                              const __nv_bfloat16* bhi, const __nv_bfloat16* blo,
                                              float acc[4][4][4], int wm, int wn, int lane) {
  const int lr = lane & 7;
  const int arofs = ((lane >> 3) & 1) * 8;
  const int akb = (lane >> 4) * 8;
  const int bkb = ((lane >> 3) & 1) * 8;
#pragma unroll
  for (int kk = 0; kk < 32; kk += 16) {
    unsigned ah[4][4], al[4][4], bh[4][2], bl[4][2];
#pragma unroll
    for (int mi = 0; mi < 4; mi++) {
      int r = wm * 64 + mi * 16 + lr + arofs;
      int s = (kk + akb) >> 3;
      ldsm4(ah[mi], ahi + SWZ(r, s));
      ldsm4(al[mi], alo + SWZ(r, s));
    }
#pragma unroll
    for (int ni = 0; ni < 4; ni++) {
      int c = (GM ? ni * 32 + wn * 8 : wn * 32 + ni * 8) + lr;
      int s = (kk + bkb) >> 3;
      ldsm2(bh[ni], bhi + SWZ(c, s));
      ldsm2(bl[ni], blo + SWZ(c, s));
    }
    // product 0: Ahi*Bhi
#pragma unroll
    for (int mi = 0; mi < 4; mi++)
#pragma unroll
      for (int ni = 0; ni < 4; ni++) mma16816(acc[mi][ni], ah[mi], bh[ni]);
    // product 1: Ahi*Blo
#pragma unroll
    for (int mi = 0; mi < 4; mi++)
#pragma unroll
      for (int ni = 0; ni < 4; ni++) mma16816(acc[mi][ni], ah[mi], bl[ni]);
    // product 2: Alo*Bhi
#pragma unroll
    for (int mi = 0; mi < 4; mi++)
#pragma unroll
      for (int ni = 0; ni < 4; ni++) mma16816(acc[mi][ni], al[mi], bh[ni]);
  }
}

__device__ __forceinline__ void st_split2(__nv_bfloat16* ph, __nv_bfloat16* pl,
                                          float x, float y) {
  __nv_bfloat16 xh = __float2bfloat16(x), yh = __float2bfloat16(y);
  __nv_bfloat162 t; t.x = xh; t.y = yh;
  *(__nv_bfloat162*)ph = t;
  __nv_bfloat162 u;
  u.x = __float2bfloat16(x - __bfloat162float(xh));
  u.y = __float2bfloat16(y - __bfloat162float(yh));
  *(__nv_bfloat162*)pl = u;
}

// ---------------------------------------------------------------------------
// Split kernels (run every call; deterministic)
// ---------------------------------------------------------------------------
__global__ void k_split_x(const float* __restrict__ xl, const float* __restrict__ xr) {
  long i = (long)blockIdx.x * NT + threadIdx.x;  // [0, 16777216) float4 groups
  long chain = i >> 23;
  long j = i & 8388607;
  float4 v = *(const float4*)((chain ? xr : xl) + j * 4);
  long o = chain * 33554432 + j * 4;
  float x[4] = {v.x, v.y, v.z, v.w};
  __nv_bfloat162 h0, h1, l0, l1;
  __nv_bfloat16 b0 = __float2bfloat16(x[0]), b1 = __float2bfloat16(x[1]);
  __nv_bfloat16 b2 = __float2bfloat16(x[2]), b3 = __float2bfloat16(x[3]);
  h0.x = b0; h0.y = b1; h1.x = b2; h1.y = b3;
  l0.x = __float2bfloat16(x[0] - __bfloat162float(b0));
  l0.y = __float2bfloat16(x[1] - __bfloat162float(b1));
  l1.x = __float2bfloat16(x[2] - __bfloat162float(b2));
  l1.y = __float2bfloat16(x[3] - __bfloat162float(b3));
  *(__nv_bfloat162*)(g_xs_hi + o) = h0;
  *(__nv_bfloat162*)(g_xs_hi + o + 2) = h1;
  *(__nv_bfloat162*)(g_xs_lo + o) = l0;
  *(__nv_bfloat162*)(g_xs_lo + o + 2) = l1;
}

__global__ void k_split_misc(const float* __restrict__ Whh_l, const float* __restrict__ Whh_r,
                             const float* __restrict__ Wih_l, const float* __restrict__ Wih_r,
                             const float* __restrict__ Wenc, const float* __restrict__ rel,
                             const float* __restrict__ bih_l, const float* __restrict__ bhh_l,
                             const float* __restrict__ bih_r, const float* __restrict__ bhh_r) {
  long idx = (long)blockIdx.x * NT + threadIdx.x;
  if (idx < 1048576) {
    // Wcomb gather: dst (((z*8+strip)*128 + (g*32+jj))*512 + k
    int k = (int)(idx & 511);
    long r2 = idx >> 9;
    int row = (int)(r2 & 127);
    int zs = (int)(r2 >> 7);
    int strip = zs & 7, z = zs >> 3;
    int g = row >> 5, jj = row & 31;
    long wrow = (long)(g * 256 + strip * 32 + jj) * 256;
    float v;
    if (k < 256) v = (z ? Whh_r : Whh_l)[wrow + k];
    else         v = (z ? Wih_r : Wih_l)[wrow + k - 256];
    __nv_bfloat16 h = __float2bfloat16(v);
    g_Wcomb_hi[idx] = h;
    g_Wcomb_lo[idx] = __float2bfloat16(v - __bfloat162float(h));
  } else if (idx < 1196032) {
    long j = idx - 1048576;
    float v = Wenc[j];
    __nv_bfloat16 h = __float2bfloat16(v);
    g_WencS_hi[j] = h;
    g_WencS_lo[j] = __float2bfloat16(v - __bfloat162float(h));
  } else if (idx < 2244608) {
    long j = idx - 1196032;
    float v = rel[j];
    __nv_bfloat16 h = __float2bfloat16(v);
    g_rels_hi[j] = h;
    g_rels_lo[j] = __float2bfloat16(v - __bfloat162float(h));
  } else if (idx < 2246656) {
    long j = idx - 2244608;  // [0,2048)
    int z = (int)(j >> 10);
    int cc = (int)(j & 1023);
    g_bsum[j] = (z ? bih_r[cc] : bih_l[cc]) + (z ? bhh_r[cc] : bhh_l[cc]);
  }
}

// Zero the h input buffers (buf 0 of each lstm) for t=0.
__global__ void k_zero_h() {
  long i = (long)blockIdx.x * NT + threadIdx.x;  // [0, 1048576) uint4 groups
  long z = i >> 19;
  long o = z * 8388608 + (i & 524287) * 8;  // elems
  uint4 zz = make_uint4(0, 0, 0, 0);
  *(uint4*)(g_hs_hi + o) = zz;
  *(uint4*)(g_hs_lo + o) = zz;
}

// ---------------------------------------------------------------------------
// Fused recurrent step t (0..7): gates = [h_{t-1} | x_t] @ Wcomb^T + bsum.
// grid (strip=8, rowTile=128, z=2). K=512 = 16 chunks (8 from h, 8 from x).
// Gate-major fragment map (ni=gate): register cell-update epilogue.
// h double-buffered: read buf[t&1], write buf[(t+1)&1]; c in place (t=0: c=0).
// ---------------------------------------------------------------------------
__device__ __forceinline__ void step_stageA(__nv_bfloat16* dh, __nv_bfloat16* dl,
                                            long rowBase, int kc, int t, int z, int tid) {
  if (kc < 8) {
    long off = ((long)z * 2 + (t & 1)) * 4194304;
    stage_pair(dh, g_hs_hi + off, rowBase, 256, kc * 32, tid);
    stage_pair(dl, g_hs_lo + off, rowBase, 256, kc * 32, tid);
  } else {
    long off = (long)z * 33554432 + t * 256;  // row n -> (n*8+t)*256
    stage_pair(dh, g_xs_hi + off, rowBase, 2048, (kc - 8) * 32, tid);
    stage_pair(dl, g_xs_lo + off, rowBase, 2048, (kc - 8) * 32, tid);
  }
}

__global__ __launch_bounds__(NT, 2) void k_step(int t) {
  extern __shared__ __nv_bfloat16 sm[];
  const int tid = threadIdx.x;
  const int z = blockIdx.z, strip = blockIdx.x;
  const long rowBase = (long)blockIdx.y * 128;
  __nv_bfloat16* hnh = g_hs_hi + ((long)z * 2 + ((t + 1) & 1)) * 4194304;
  __nv_bfloat16* hnl = g_hs_lo + ((long)z * 2 + ((t + 1) & 1)) * 4194304;
  float* cst = g_c + (long)z * 4194304;
  const long bRow = (long)(z * 8 + strip) * 128;

  const int wid = tid >> 5, lane = tid & 31;
  const int wm = wid & 1, wn = wid >> 1;
  const int qr = lane >> 2, qc = (lane & 3) << 1;

  float acc[4][4][4];
#pragma unroll
  for (int a = 0; a < 4; a++)
#pragma unroll
    for (int b = 0; b < 4; b++)
#pragma unroll
      for (int q = 0; q < 4; q++) acc[a][b][q] = 0.0f;

  {
    __nv_bfloat16* base = sm;
    step_stageA(base, base + ARR, rowBase, 0, t, z, tid);
    stage_pair(base + 2 * ARR, g_Wcomb_hi, bRow, 512, 0, tid);
    stage_pair(base + 3 * ARR, g_Wcomb_lo, bRow, 512, 0, tid);
    CP_COMMIT;
  }
  for (int kc = 0; kc < 16; kc++) {
    CP_WAIT0;
    __syncthreads();
    if (kc + 1 < 16) {
      __nv_bfloat16* base = sm + ((kc + 1) & 1) * BUFSZ;
      step_stageA(base, base + ARR, rowBase, kc + 1, t, z, tid);
      stage_pair(base + 2 * ARR, g_Wcomb_hi, bRow, 512, (kc + 1) * 32, tid);
      stage_pair(base + 3 * ARR, g_Wcomb_lo, bRow, 512, (kc + 1) * 32, tid);
      CP_COMMIT;
    }
    const __nv_bfloat16* base = sm + (kc & 1) * BUFSZ;
    compute_chunk<true>(base, base + ARR, base + 2 * ARR, base + 3 * ARR, acc, wm, wn, lane);
  }

  // register epilogue: ni -> gate (i,f,g,o) of j = strip*32 + wn*8 + qc
  const int jloc = strip * 32 + wn * 8 + qc;
  const float* bs = g_bsum + z * 1024;
  const float2 bi2 = *(const float2*)(bs + jloc);
  const float2 bf2 = *(const float2*)(bs + 256 + jloc);
  const float2 bg2 = *(const float2*)(bs + 512 + jloc);
  const float2 bo2 = *(const float2*)(bs + 768 + jloc);
#pragma unroll
  for (int mi = 0; mi < 4; mi++) {
#pragma unroll
    for (int hh = 0; hh < 2; hh++) {
      const long n = rowBase + wm * 64 + mi * 16 + qr + hh * 8;
      float2 cp2 = make_float2(0.0f, 0.0f);
      if (t) cp2 = *(const float2*)(cst + n * 256 + jloc);
      const int b = hh * 2;
      float gi0 = acc[mi][0][b] + bi2.x, gi1 = acc[mi][0][b + 1] + bi2.y;
      float gf0 = acc[mi][1][b] + bf2.x, gf1 = acc[mi][1][b + 1] + bf2.y;
      float gg0 = acc[mi][2][b] + bg2.x, gg1 = acc[mi][2][b + 1] + bg2.y;
      float go0 = acc[mi][3][b] + bo2.x, go1 = acc[mi][3][b + 1] + bo2.y;
      float c0 = fsig(gf0) * cp2.x + fsig(gi0) * ftanh(gg0);
      float c1 = fsig(gf1) * cp2.y + fsig(gi1) * ftanh(gg1);
      *(float2*)(cst + n * 256 + jloc) = make_float2(c0, c1);
      float h0 = fsig(go0) * ftanh(c0);
      float h1 = fsig(go1) * ftanh(c1);
      st_split2(hnh + n * 256 + jloc, hnl + n * 256 + jloc, h0, h1);
    }
  }
}

// ---------------------------------------------------------------------------
// Encoder: out = tanh([hl, hr, rel] @ Wenc^T + benc). grid (colTile=2, rowTile=128)
// K = 576 = 18 chunks; A source hl -> hr -> rel. Final h in buf 0.
// ---------------------------------------------------------------------------
__device__ __forceinline__ void enc_stageA(__nv_bfloat16* dh, __nv_bfloat16* dl,
                                           long rowBase, int kc, int tid) {
  const __nv_bfloat16 *sh, *sl;
  int ld, koff;
  if (kc < 8)       { sh = g_hs_hi;                sl = g_hs_lo;                ld = 256; koff = kc * 32; }
  else if (kc < 16) { sh = g_hs_hi + 2L * 4194304; sl = g_hs_lo + 2L * 4194304; ld = 256; koff = (kc - 8) * 32; }
  else              { sh = g_rels_hi;              sl = g_rels_lo;              ld = 64;  koff = (kc - 16) * 32; }
  stage_pair(dh, sh, rowBase, ld, koff, tid);
  stage_pair(dl, sl, rowBase, ld, koff, tid);
}

__global__ __launch_bounds__(NT, 2) void k_enc(const float* __restrict__ benc,
                                               float* __restrict__ out) {
  extern __shared__ __nv_bfloat16 sm[];
  const int tid = threadIdx.x;
  const int colTile = blockIdx.x;
  const long rowBase = (long)blockIdx.y * 128;
  const long bRow = (long)colTile * 128;

  const int wid = tid >> 5, lane = tid & 31;
  const int wm = wid & 1, wn = wid >> 1;
  const int qr = lane >> 2, qc = (lane & 3) << 1;

  float acc[4][4][4];
#pragma unroll
  for (int a = 0; a < 4; a++)
#pragma unroll
    for (int b = 0; b < 4; b++)
#pragma unroll
      for (int q = 0; q < 4; q++) acc[a][b][q] = 0.0f;

  {
    __nv_bfloat16* base = sm;
    enc_stageA(base, base + ARR, rowBase, 0, tid);
    stage_pair(base + 2 * ARR, g_WencS_hi, bRow, 576, 0, tid);
    stage_pair(base + 3 * ARR, g_WencS_lo, bRow, 576, 0, tid);
    CP_COMMIT;
  }
  for (int kc = 0; kc < 18; kc++) {
    CP_WAIT0;
    __syncthreads();
    if (kc + 1 < 18) {
      __nv_bfloat16* base = sm + ((kc + 1) & 1) * BUFSZ;
      enc_stageA(base, base + ARR, rowBase, kc + 1, tid);
      stage_pair(base + 2 * ARR, g_WencS_hi, bRow, 576, (kc + 1) * 32, tid);
      stage_pair(base + 3 * ARR, g_WencS_lo, bRow, 576, (kc + 1) * 32, tid);
      CP_COMMIT;
    }
    const __nv_bfloat16* base = sm + (kc & 1) * BUFSZ;
    compute_chunk<false>(base, base + ARR, base + 2 * ARR, base + 3 * ARR, acc, wm, wn, lane);
  }

#pragma unroll
  for (int mi = 0; mi < 4; mi++) {
#pragma unroll
    for (int hh = 0; hh < 2; hh++) {
      long n = rowBase + wm * 64 + mi * 16 + qr + hh * 8;
#pragma unroll
      for (int ni = 0; ni < 4; ni++) {
        int col = colTile * 128 + wn * 32 + ni * 8 + qc;
        float2 b2 = *(const float2*)(benc + col);
        float v0 = ftanh(acc[mi][ni][hh * 2] + b2.x);
        float v1 = ftanh(acc[mi][ni][hh * 2 + 1] + b2.y);
        *(float2*)(out + n * 256 + col) = make_float2(v0, v1);
      }
    }
  }
}

// ---------------------------------------------------------------------------
extern "C" void kernel_launch(void* const* d_in, const int* in_sizes, int n_in,
                              void* d_out, int out_size) {
  (void)in_sizes; (void)n_in; (void)out_size;
  const float* left  = (const float*)d_in[0];
  const float* right = (const float*)d_in[1];
  const float* rel   = (const float*)d_in[2];
  const float* Wih_l = (const float*)d_in[3];
  const float* Whh_l = (const float*)d_in[4];
  const float* bih_l = (const float*)d_in[5];
  const float* bhh_l = (const float*)d_in[6];
  const float* Wih_r = (const float*)d_in[7];
  const float* Whh_r = (const float*)d_in[8];
  const float* bih_r = (const float*)d_in[9];
  const float* bhh_r = (const float*)d_in[10];
  const float* Wenc  = (const float*)d_in[11];
  const float* benc  = (const float*)d_in[12];
  float* out = (float*)d_out;

  cudaFuncSetAttribute(k_step, cudaFuncAttributeMaxDynamicSharedMemorySize, SMEM_BYTES);
  cudaFuncSetAttribute(k_enc, cudaFuncAttributeMaxDynamicSharedMemorySize, SMEM_BYTES);

  k_split_x<<<65536, NT>>>(left, right);
  k_split_misc<<<8776, NT>>>(Whh_l, Whh_r, Wih_l, Wih_r, Wenc, rel,
                             bih_l, bhh_l, bih_r, bhh_r);
  k_zero_h<<<4096, NT>>>();
  for (int t = 0; t < 8; t++)
    k_step<<<dim3(8, 128, 2), NT, SMEM_BYTES>>>(t);
  k_enc<<<dim3(2, 128), NT, SMEM_BYTES>>>(benc, out);
}

// round 13
// speedup vs baseline: 2.7349x; 1.0678x over previous
#include <cuda_runtime.h>
#include <cuda_bf16.h>
#include <math.h>

// N=16384 nodes, L=8, D=256, H=256, R=64. Gate order i,f,g,o.
// Fused recurrence: gates_t = [h_{t-1} | x_t] @ [Whh | Wih]^T + b (K=512 GEMM
// per step; t=0 uses x-only K=256 since h0=0). mma.sync bf16 hi/lo split
// (3 products), XOR-swizzled smem, 3-stage cp.async pipeline (96KB/CTA,
// 2 CTAs/SM), merged-B ldmatrix, product-outer MMA order, register epilogues.

#define NT 256

// ------------------------- device scratch (no allocs) -----------------------
__device__ float g_c[8388608];               // [2][16384][256] cell state fp32
__device__ __nv_bfloat16 g_hs_hi[16777216];  // [2 lstm][2 buf][16384][256]
__device__ __nv_bfloat16 g_hs_lo[16777216];
__device__ __nv_bfloat16 g_xs_hi[67108864];  // [2 chain][16384*8 (n*8+l)][256]
__device__ __nv_bfloat16 g_xs_lo[67108864];
__device__ __nv_bfloat16 g_Wcomb_hi[1048576]; // [2][8 strip][128(g*32+jj)][512(Whh|Wih)]
__device__ __nv_bfloat16 g_Wcomb_lo[1048576];
__device__ __nv_bfloat16 g_WencS_hi[147456];  // [256][576]
__device__ __nv_bfloat16 g_WencS_lo[147456];
__device__ __nv_bfloat16 g_rels_hi[1048576];  // [16384][64]
__device__ __nv_bfloat16 g_rels_lo[1048576];
__device__ float g_bsum[2048];                // [2][1024] bih+bhh

// ------------------------------- helpers ------------------------------------
__device__ __forceinline__ float fsig(float x) {
  return __fdividef(1.0f, 1.0f + __expf(-x));
}
__device__ __forceinline__ float ftanh(float x) {
  return 2.0f * __fdividef(1.0f, 1.0f + __expf(-2.0f * x)) - 1.0f;
}

__device__ __forceinline__ void mma16816(float* d, const unsigned* a, const unsigned* b) {
  asm volatile(
      "mma.sync.aligned.m16n8k16.row.col.f32.bf16.bf16.f32 "
      "{%0,%1,%2,%3}, {%4,%5,%6,%7}, {%8,%9}, {%0,%1,%2,%3};\n"
      : "+f"(d[0]), "+f"(d[1]), "+f"(d[2]), "+f"(d[3])
      : "r"(a[0]), "r"(a[1]), "r"(a[2]), "r"(a[3]), "r"(b[0]), "r"(b[1]));
}
__device__ __forceinline__ void ldsm4(unsigned* r, const __nv_bfloat16* p) {
  unsigned a = (unsigned)__cvta_generic_to_shared(p);
  asm volatile("ldmatrix.sync.aligned.m8n8.x4.shared.b16 {%0,%1,%2,%3}, [%4];\n"
               : "=r"(r[0]), "=r"(r[1]), "=r"(r[2]), "=r"(r[3]) : "r"(a));
}
__device__ __forceinline__ void cpa16(void* dst, const void* src) {
  unsigned s = (unsigned)__cvta_generic_to_shared(dst);
  asm volatile("cp.async.cg.shared.global [%0], [%1], 16;\n" :: "r"(s), "l"(src));
}
#define CP_COMMIT asm volatile("cp.async.commit_group;\n")
template <int N>
__device__ __forceinline__ void cp_wait() {
  asm volatile("cp.async.wait_group %0;\n" :: "n"(N));
}

// XOR-swizzled smem layout: array [128 rows][32 bf16] (64B rows, no pad).
// Element offset for (row r, 16B-seg s in 0..3): r*32 + ((s ^ ((r>>1)&3))<<3).
#define SWZ(r, s) ((r) * 32 + ((((s) ^ (((r) >> 1) & 3))) << 3))
#define ARR 4096     // 128*32 elems per array
#define BUFSZ 16384  // 4*ARR elems per buffer (32KB)
#define NSTAGE 3
#define SMEM_BYTES 98304  // 3 stages x 32KB

// stage one 128x32 bf16 chunk: 512 16B segs, 2 per thread
__device__ __forceinline__ void stage_pair(__nv_bfloat16* d, const __nv_bfloat16* s,
                                           long rowBase, int ld, int koff, int tid) {
#pragma unroll
  for (int i = 0; i < 2; i++) {
    int f = tid + i * NT;
    int row = f >> 2, seg = f & 3;
    cpa16(d + SWZ(row, seg), s + (rowBase + row) * (long)ld + koff + seg * 8);
  }
}

// GM=true: B smem row c = ni*32 + wn*8 + qr (gate-major cols)
// GM=false: c = wn*32 + ni*8 + qr (plain cols)
// B hi+lo merged into one ldsm4: tiles [bhi k, bhi k+8, blo k, blo k+8] via
// lane groups (0-7: bhi/k, 8-15: bhi/k+8, 16-23: blo/k, 24-31: blo/k+8).
// Product-outer MMA order: same-acc MMAs separated by 16 independent issues.
template <bool GM>
__device__ __forceinline__ void compute_chunk(const __nv_bfloat16* ahi, const __nv_bfloat16* alo,
                                              const __nv_bfloat16* bhi, const __nv_bfloat16* blo,
                                              float acc[4][4][4], int wm, int wn, int lane) {
  const int lr = lane & 7;
  const int arofs = ((lane >> 3) & 1) * 8;
  const int akb = (lane >> 4) * 8;
  const int bksel = (lane >> 3) & 1;
  const __nv_bfloat16* bbase = (lane >= 16) ? blo : bhi;
#pragma unroll
  for (int kk = 0; kk < 32; kk += 16) {
    unsigned ah[4][4], al[4][4], bb[4][4];
#pragma unroll
    for (int mi = 0; mi < 4; mi++) {
      int r = wm * 64 + mi * 16 + lr + arofs;
      int s = (kk + akb) >> 3;
      ldsm4(ah[mi], ahi + SWZ(r, s));
      ldsm4(al[mi], alo + SWZ(r, s));
    }
#pragma unroll
    for (int ni = 0; ni < 4; ni++) {
      int c = (GM ? ni * 32 + wn * 8 : wn * 32 + ni * 8) + lr;
      ldsm4(bb[ni], bbase + SWZ(c, (kk >> 3) + bksel));
    }
    // product 0: Ahi*Bhi
#pragma unroll
    for (int mi = 0; mi < 4; mi++)
#pragma unroll
      for (int ni = 0; ni < 4; ni++) mma16816(acc[mi][ni], ah[mi], &bb[ni][0]);
    // product 1: Ahi*Blo
#pragma unroll
    for (int mi = 0; mi < 4; mi++)
#pragma unroll
      for (int ni = 0; ni < 4; ni++) mma16816(acc[mi][ni], ah[mi], &bb[ni][2]);
    // product 2: Alo*Bhi
#pragma unroll
    for (int mi = 0; mi < 4; mi++)
#pragma unroll
      for (int ni = 0; ni < 4; ni++) mma16816(acc[mi][ni], al[mi], &bb[ni][0]);
  }
}

__device__ __forceinline__ void st_split2(__nv_bfloat16* ph, __nv_bfloat16* pl,
                                          float x, float y) {
  __nv_bfloat16 xh = __float2bfloat16(x), yh = __float2bfloat16(y);
  __nv_bfloat162 t; t.x = xh; t.y = yh;
  *(__nv_bfloat162*)ph = t;
  __nv_bfloat162 u;
  u.x = __float2bfloat16(x - __bfloat162float(xh));
  u.y = __float2bfloat16(y - __bfloat162float(yh));
  *(__nv_bfloat162*)pl = u;
}

// ---------------------------------------------------------------------------
// Split kernels (run every call; deterministic)
// ---------------------------------------------------------------------------
__global__ void k_split_x(const float* __restrict__ xl, const float* __restrict__ xr) {
  long i = (long)blockIdx.x * NT + threadIdx.x;  // [0, 16777216) float4 groups
  long chain = i >> 23;
  long j = i & 8388607;
  float4 v = *(const float4*)((chain ? xr : xl) + j * 4);
  long o = chain * 33554432 + j * 4;
  float x[4] = {v.x, v.y, v.z, v.w};
  __nv_bfloat162 h0, h1, l0, l1;
  __nv_bfloat16 b0 = __float2bfloat16(x[0]), b1 = __float2bfloat16(x[1]);
  __nv_bfloat16 b2 = __float2bfloat16(x[2]), b3 = __float2bfloat16(x[3]);
  h0.x = b0; h0.y = b1; h1.x = b2; h1.y = b3;
  l0.x = __float2bfloat16(x[0] - __bfloat162float(b0));
  l0.y = __float2bfloat16(x[1] - __bfloat162float(b1));
  l1.x = __float2bfloat16(x[2] - __bfloat162float(b2));
  l1.y = __float2bfloat16(x[3] - __bfloat162float(b3));
  *(__nv_bfloat162*)(g_xs_hi + o) = h0;
  *(__nv_bfloat162*)(g_xs_hi + o + 2) = h1;
  *(__nv_bfloat162*)(g_xs_lo + o) = l0;
  *(__nv_bfloat162*)(g_xs_lo + o + 2) = l1;
}

__global__ void k_split_misc(const float* __restrict__ Whh_l, const float* __restrict__ Whh_r,
                             const float* __restrict__ Wih_l, const float* __restrict__ Wih_r,
                             const float* __restrict__ Wenc, const float* __restrict__ rel,
                             const float* __restrict__ bih_l, const float* __restrict__ bhh_l,
                             const float* __restrict__ bih_r, const float* __restrict__ bhh_r) {
  long idx = (long)blockIdx.x * NT + threadIdx.x;
  if (idx < 1048576) {
    // Wcomb gather: dst (((z*8+strip)*128 + (g*32+jj))*512 + k
    int k = (int)(idx & 511);
    long r2 = idx >> 9;
    int row = (int)(r2 & 127);
    int zs = (int)(r2 >> 7);
    int strip = zs & 7, z = zs >> 3;
    int g = row >> 5, jj = row & 31;
    long wrow = (long)(g * 256 + strip * 32 + jj) * 256;
    float v;
    if (k < 256) v = (z ? Whh_r : Whh_l)[wrow + k];
    else         v = (z ? Wih_r : Wih_l)[wrow + k - 256];
    __nv_bfloat16 h = __float2bfloat16(v);
    g_Wcomb_hi[idx] = h;
    g_Wcomb_lo[idx] = __float2bfloat16(v - __bfloat162float(h));
  } else if (idx < 1196032) {
    long j = idx - 1048576;
    float v = Wenc[j];
    __nv_bfloat16 h = __float2bfloat16(v);
    g_WencS_hi[j] = h;
    g_WencS_lo[j] = __float2bfloat16(v - __bfloat162float(h));
  } else if (idx < 2244608) {
    long j = idx - 1196032;
    float v = rel[j];
    __nv_bfloat16 h = __float2bfloat16(v);
    g_rels_hi[j] = h;
    g_rels_lo[j] = __float2bfloat16(v - __bfloat162float(h));
  } else if (idx < 2246656) {
    long j = idx - 2244608;  // [0,2048)
    int z = (int)(j >> 10);
    int cc = (int)(j & 1023);
    g_bsum[j] = (z ? bih_r[cc] : bih_l[cc]) + (z ? bhh_r[cc] : bhh_l[cc]);
  }
}

// ---------------------------------------------------------------------------
// Fused recurrent step t (0..7): gates = [h_{t-1} | x_t] @ Wcomb^T + bsum.
// grid (strip=8, rowTile=128, z=2). K=512 = 16 chunks (8 h + 8 x); t=0 skips
// the h chunks (h0=0 contributes nothing). 3-stage cp.async pipeline.
// Gate-major fragment map (ni=gate): register cell-update epilogue.
// ---------------------------------------------------------------------------
__device__ __forceinline__ void step_stageA(__nv_bfloat16* dh, __nv_bfloat16* dl,
                                            long rowBase, int kc, int t, int z, int tid) {
  if (kc < 8) {
    long off = ((long)z * 2 + (t & 1)) * 4194304;
    stage_pair(dh, g_hs_hi + off, rowBase, 256, kc * 32, tid);
    stage_pair(dl, g_hs_lo + off, rowBase, 256, kc * 32, tid);
  } else {
    long off = (long)z * 33554432 + t * 256;  // row n -> (n*8+t)*256
    stage_pair(dh, g_xs_hi + off, rowBase, 2048, (kc - 8) * 32, tid);
    stage_pair(dl, g_xs_lo + off, rowBase, 2048, (kc - 8) * 32, tid);
  }
}

__device__ __forceinline__ void step_stage_full(__nv_bfloat16* base, long rowBase,
                                                long bRow, int kc, int t, int z, int tid) {
  step_stageA(base, base + ARR, rowBase, kc, t, z, tid);
  stage_pair(base + 2 * ARR, g_Wcomb_hi, bRow, 512, kc * 32, tid);
  stage_pair(base + 3 * ARR, g_Wcomb_lo, bRow, 512, kc * 32, tid);
}

__global__ __launch_bounds__(NT, 2) void k_step(int t) {
  extern __shared__ __nv_bfloat16 sm[];
  const int tid = threadIdx.x;
  const int z = blockIdx.z, strip = blockIdx.x;
  const long rowBase = (long)blockIdx.y * 128;
  __nv_bfloat16* hnh = g_hs_hi + ((long)z * 2 + ((t + 1) & 1)) * 4194304;
  __nv_bfloat16* hnl = g_hs_lo + ((long)z * 2 + ((t + 1) & 1)) * 4194304;
  float* cst = g_c + (long)z * 4194304;
  const long bRow = (long)(z * 8 + strip) * 128;

  const int wid = tid >> 5, lane = tid & 31;
  const int wm = wid & 1, wn = wid >> 1;
  const int qr = lane >> 2, qc = (lane & 3) << 1;

  const int kc0 = (t == 0) ? 8 : 0;   // t=0: x chunks only (h0 = 0)
  const int NK = 16 - kc0;

  float acc[4][4][4];
#pragma unroll
  for (int a = 0; a < 4; a++)
#pragma unroll
    for (int b = 0; b < 4; b++)
#pragma unroll
      for (int q = 0; q < 4; q++) acc[a][b][q] = 0.0f;

  // prologue: stage chunks kc0, kc0+1 into stages 0, 1
  step_stage_full(sm, rowBase, bRow, kc0, t, z, tid);
  CP_COMMIT;
  step_stage_full(sm + BUFSZ, rowBase, bRow, kc0 + 1, t, z, tid);
  CP_COMMIT;

  int stg = 0, stg2 = 2;  // stage of chunk i, stage of chunk i+2
  for (int i = 0; i < NK; i++) {
    cp_wait<1>();
    __syncthreads();
    if (i + 2 < NK)
      step_stage_full(sm + stg2 * BUFSZ, rowBase, bRow, kc0 + i + 2, t, z, tid);
    CP_COMMIT;
    const __nv_bfloat16* base = sm + stg * BUFSZ;
    compute_chunk<true>(base, base + ARR, base + 2 * ARR, base + 3 * ARR, acc, wm, wn, lane);
    stg = (stg == 2) ? 0 : stg + 1;
    stg2 = (stg2 == 2) ? 0 : stg2 + 1;
  }

  // register epilogue: ni -> gate (i,f,g,o) of j = strip*32 + wn*8 + qc
  const int jloc = strip * 32 + wn * 8 + qc;
  const float* bs = g_bsum + z * 1024;
  const float2 bi2 = *(const float2*)(bs + jloc);
  const float2 bf2 = *(const float2*)(bs + 256 + jloc);
  const float2 bg2 = *(const float2*)(bs + 512 + jloc);
  const float2 bo2 = *(const float2*)(bs + 768 + jloc);
#pragma unroll
  for (int mi = 0; mi < 4; mi++) {
#pragma unroll
    for (int hh = 0; hh < 2; hh++) {
      const long n = rowBase + wm * 64 + mi * 16 + qr + hh * 8;
      float2 cp2 = make_float2(0.0f, 0.0f);
      if (t) cp2 = *(const float2*)(cst + n * 256 + jloc);
      const int b = hh * 2;
      float gi0 = acc[mi][0][b] + bi2.x, gi1 = acc[mi][0][b + 1] + bi2.y;
      float gf0 = acc[mi][1][b] + bf2.x, gf1 = acc[mi][1][b + 1] + bf2.y;
      float gg0 = acc[mi][2][b] + bg2.x, gg1 = acc[mi][2][b + 1] + bg2.y;
      float go0 = acc[mi][3][b] + bo2.x, go1 = acc[mi][3][b + 1] + bo2.y;
      float c0 = fsig(gf0) * cp2.x + fsig(gi0) * ftanh(gg0);
      float c1 = fsig(gf1) * cp2.y + fsig(gi1) * ftanh(gg1);
      *(float2*)(cst + n * 256 + jloc) = make_float2(c0, c1);
      float h0 = fsig(go0) * ftanh(c0);
      float h1 = fsig(go1) * ftanh(c1);
      st_split2(hnh + n * 256 + jloc, hnl + n * 256 + jloc, h0, h1);
    }
  }
}

// ---------------------------------------------------------------------------
// Encoder: out = tanh([hl, hr, rel] @ Wenc^T + benc). grid (colTile=2, rowTile=128)
// K = 576 = 18 chunks; A source hl -> hr -> rel. Final h in buf 0.
// ---------------------------------------------------------------------------
__device__ __forceinline__ void enc_stage_full(__nv_bfloat16* base, long rowBase,
                                               long bRow, int kc, int tid) {
  const __nv_bfloat16 *sh, *sl;
  int ld, koff;
  if (kc < 8)       { sh = g_hs_hi;                sl = g_hs_lo;                ld = 256; koff = kc * 32; }
  else if (kc < 16) { sh = g_hs_hi + 2L * 4194304; sl = g_hs_lo + 2L * 4194304; ld = 256; koff = (kc - 8) * 32; }
  else              { sh = g_rels_hi;              sl = g_rels_lo;              ld = 64;  koff = (kc - 16) * 32; }
  stage_pair(base, sh, rowBase, ld, koff, tid);
  stage_pair(base + ARR, sl, rowBase, ld, koff, tid);
  stage_pair(base + 2 * ARR, g_WencS_hi, bRow, 576, kc * 32, tid);
  stage_pair(base + 3 * ARR, g_WencS_lo, bRow, 576, kc * 32, tid);
}

__global__ __launch_bounds__(NT, 2) void k_enc(const float* __restrict__ benc,
                                               float* __restrict__ out) {
  extern __shared__ __nv_bfloat16 sm[];
  const int tid = threadIdx.x;
  const int colTile = blockIdx.x;
  const long rowBase = (long)blockIdx.y * 128;
  const long bRow = (long)colTile * 128;

  const int wid = tid >> 5, lane = tid & 31;
  const int wm = wid & 1, wn = wid >> 1;
  const int qr = lane >> 2, qc = (lane & 3) << 1;

  float acc[4][4][4];
#pragma unroll
  for (int a = 0; a < 4; a++)
#pragma unroll
    for (int b = 0; b < 4; b++)
#pragma unroll
      for (int q = 0; q < 4; q++) acc[a][b][q] = 0.0f;

  enc_stage_full(sm, rowBase, bRow, 0, tid);
  CP_COMMIT;
  enc_stage_full(sm + BUFSZ, rowBase, bRow, 1, tid);
  CP_COMMIT;

  int stg = 0, stg2 = 2;
  for (int i = 0; i < 18; i++) {
    cp_wait<1>();
    __syncthreads();
    if (i + 2 < 18)
      enc_stage_full(sm + stg2 * BUFSZ, rowBase, bRow, i + 2, tid);
    CP_COMMIT;
    const __nv_bfloat16* base = sm + stg * BUFSZ;
    compute_chunk<false>(base, base + ARR, base + 2 * ARR, base + 3 * ARR, acc, wm, wn, lane);
    stg = (stg == 2) ? 0 : stg + 1;
    stg2 = (stg2 == 2) ? 0 : stg2 + 1;
  }

#pragma unroll
  for (int mi = 0; mi < 4; mi++) {
#pragma unroll
    for (int hh = 0; hh < 2; hh++) {
      long n = rowBase + wm * 64 + mi * 16 + qr + hh * 8;
#pragma unroll
      for (int ni = 0; ni < 4; ni++) {
        int col = colTile * 128 + wn * 32 + ni * 8 + qc;
        float2 b2 = *(const float2*)(benc + col);
        float v0 = ftanh(acc[mi][ni][hh * 2] + b2.x);
        float v1 = ftanh(acc[mi][ni][hh * 2 + 1] + b2.y);
        *(float2*)(out + n * 256 + col) = make_float2(v0, v1);
      }
    }
  }
}

// ---------------------------------------------------------------------------
extern "C" void kernel_launch(void* const* d_in, const int* in_sizes, int n_in,
                              void* d_out, int out_size) {
  (void)in_sizes; (void)n_in; (void)out_size;
  const float* left  = (const float*)d_in[0];
  const float* right = (const float*)d_in[1];
  const float* rel   = (const float*)d_in[2];
  const float* Wih_l = (const float*)d_in[3];
  const float* Whh_l = (const float*)d_in[4];
  const float* bih_l = (const float*)d_in[5];
  const float* bhh_l = (const float*)d_in[6];
  const float* Wih_r = (const float*)d_in[7];
  const float* Whh_r = (const float*)d_in[8];
  const float* bih_r = (const float*)d_in[9];
  const float* bhh_r = (const float*)d_in[10];
  const float* Wenc  = (const float*)d_in[11];
  const float* benc  = (const float*)d_in[12];
  float* out = (float*)d_out;

  cudaFuncSetAttribute(k_step, cudaFuncAttributeMaxDynamicSharedMemorySize, SMEM_BYTES);
  cudaFuncSetAttribute(k_enc, cudaFuncAttributeMaxDynamicSharedMemorySize, SMEM_BYTES);

  k_split_x<<<65536, NT>>>(left, right);
  k_split_misc<<<8776, NT>>>(Whh_l, Whh_r, Wih_l, Wih_r, Wenc, rel,
                             bih_l, bhh_l, bih_r, bhh_r);
  for (int t = 0; t < 8; t++)
    k_step<<<dim3(8, 128, 2), NT, SMEM_BYTES>>>(t);
  k_enc<<<dim3(2, 128), NT, SMEM_BYTES>>>(benc, out);
}